// round 12
// baseline (speedup 1.0000x reference)
#include <cuda_runtime.h>
#include <cuda_fp16.h>
#include <math.h>
#include <stdint.h>

#define BATCH 4
#define CINC 2048
#define HH 65
#define HP (HH*HH)          // 4225
#define INNERC 256
#define NCAT 1280
#define NCCL 19
#define QLL 2975
#define ROWS (BATCH*HP)     // 16900
#define NSLICE 512
#define RSLICE 64
#define LCHUNK 128
#define NLCH 24             // ceil(2975/128)
#define NPB 133             // ceil(HP/32) pixel blocks for gp partials

// ------------------------- static scratch (no allocation allowed) -------------------------
static __device__ __half sc_xh[(size_t)BATCH*HP*CINC];
static __device__ __half sc_aspp_rawh[(size_t)BATCH*HP*1024];    // pre-BN conv branches, fp16
static __device__ __half sc_asppH[(size_t)BATCH*HP*NCAT];
static __device__ float sc_fea[(size_t)BATCH*HP*INNERC];         // pre-BN head conv out
// blocked fp16 weights: [stage=(t,cc32)][256 co][32 ci]
static __device__ __half sc_w1h[CINC*INNERC];
static __device__ __half sc_w12h[9*CINC*INNERC];
static __device__ __half sc_w24h[9*CINC*INNERC];
static __device__ __half sc_w36h[9*CINC*INNERC];
static __device__ __half sc_whh[9*NCAT*INNERC];
static __device__ float sc_gpp[BATCH*NPB*CINC];              // gp partial sums
static __device__ float sc_gpv[BATCH*CINC];
static __device__ float sc_z0[BATCH*INNERC];
static __device__ float sc_br0[BATCH*INNERC];
static __device__ float sc_psum[NSLICE*1024];
static __device__ float sc_psq[NSLICE*1024];
static __device__ float sc_mean[1024];
static __device__ float sc_invstd[1024];
static __device__ float sc_mean2[INNERC];
static __device__ float sc_invstd2[INNERC];
static __device__ int   sc_pred[ROWS];
static __device__ float sc_rpsum[RSLICE*NCCL*INNERC];
static __device__ float sc_rpcnt[RSLICE*NCCL];
static __device__ float sc_keys[NCCL*INNERC];
static __device__ float sc_counts[NCCL];
static __device__ float sc_psume[NCCL*NCCL*NLCH];
static __device__ float sc_adiag[NCCL*QLL];

// ------------------------- helpers -------------------------
__device__ __forceinline__ uint32_t smem_u32(const void* p) {
    uint32_t a;
    asm("{ .reg .u64 t; cvta.to.shared.u64 t, %1; cvt.u32.u64 %0, t; }" : "=r"(a) : "l"(p));
    return a;
}
// 64B-row swizzle: XOR row bits (1,2) into 16B-granule bits
__device__ __forceinline__ uint32_t sw64(uint32_t off) { return off ^ ((off >> 3) & 0x30); }

__device__ __forceinline__ void cp16(uint32_t dst, const void* src, int sz) {
    asm volatile("cp.async.cg.shared.global [%0], [%1], 16, %2;"
                 :: "r"(dst), "l"(src), "r"(sz) : "memory");
}
#define CP_COMMIT() asm volatile("cp.async.commit_group;" ::: "memory")
#define CP_WAIT2()  asm volatile("cp.async.wait_group 2;" ::: "memory")

__device__ __forceinline__ void ldsm4(uint32_t* r, uint32_t addr) {
    asm volatile("ldmatrix.sync.aligned.m8n8.x4.shared.b16 {%0,%1,%2,%3}, [%4];"
                 : "=r"(r[0]), "=r"(r[1]), "=r"(r[2]), "=r"(r[3]) : "r"(addr));
}
__device__ __forceinline__ void mma16816(float* d, const uint32_t* a, uint32_t b0, uint32_t b1) {
    asm volatile("mma.sync.aligned.m16n8k16.row.col.f32.f16.f16.f32 "
                 "{%0,%1,%2,%3}, {%4,%5,%6,%7}, {%8,%9}, {%0,%1,%2,%3};"
                 : "+f"(d[0]), "+f"(d[1]), "+f"(d[2]), "+f"(d[3])
                 : "r"(a[0]), "r"(a[1]), "r"(a[2]), "r"(a[3]), "r"(b0), "r"(b1));
}
__device__ __forceinline__ void store2(float* p, float a, float b) { *(float2*)p = make_float2(a, b); }
__device__ __forceinline__ void store2(__half* p, float a, float b) { *(__half2*)p = __floats2half2_rn(a, b); }
__device__ __forceinline__ float ldf(const float* p) { return *p; }
__device__ __forceinline__ float ldf(const __half* p) { return __half2float(*p); }

struct ConvCfg {
    const __half* wh[4];
    int ntaps[4];
    int dil[4];
    int off[4];
};
struct WtCfg {
    const float* src[5];
    __half* dh[5];
    int Cin[5];
    int ntaps[5];
    int base[6];
};

// ------------------------- pre kernels -------------------------

// NCHW -> [b][p][ci] fp16 + global-pool partial sums
__global__ void transpose_x_fp16_kernel(const float* __restrict__ x,
                                        __half* __restrict__ xh, float* __restrict__ gpp)
{
    __shared__ float tile[32][33];
    __shared__ float red[32][8];
    int b = blockIdx.z;
    int p0 = blockIdx.x * 32, c0 = blockIdx.y * 32;
    int tx = threadIdx.x, ty = threadIdx.y; // 32 x 8
    #pragma unroll
    for (int i = 0; i < 32; i += 8) {
        int c = c0 + ty + i, p = p0 + tx;
        tile[ty + i][tx] = (p < HP) ? x[((size_t)b*CINC + c)*HP + p] : 0.f;
    }
    __syncthreads();
    #pragma unroll
    for (int i = 0; i < 32; i += 8) {
        int p = p0 + ty + i, c = c0 + tx;
        if (p < HP)
            xh[((size_t)b*HP + p)*CINC + c] = __float2half(tile[tx][ty + i]);
    }
    {
        float s = 0.f;
        #pragma unroll
        for (int j = 0; j < 4; j++) s += tile[tx][ty*4 + j];
        red[tx][ty] = s;
        __syncthreads();
        if (ty == 0) {
            float t = 0.f;
            #pragma unroll
            for (int k = 0; k < 8; k++) t += red[tx][k];
            gpp[((size_t)b*NPB + blockIdx.x)*CINC + c0 + tx] = t;
        }
    }
}

__global__ void gp_final_kernel(const float* __restrict__ gpp, float* __restrict__ gpv)
{
    int idx = blockIdx.x * 256 + threadIdx.x;   // (b,c)
    if (idx >= BATCH*CINC) return;
    int b = idx >> 11, c = idx & 2047;
    float s = 0.f;
    for (int k = 0; k < NPB; k++) s += gpp[((size_t)b*NPB + k)*CINC + c];
    gpv[idx] = s / (float)HP;
}

// all five weight transforms in one launch: w[co][ci][t] -> [stage=(t,cc32)][co 256][ci 32] fp16
__global__ void wtrans_all_kernel(WtCfg cfg)
{
    int idx = blockIdx.x * 256 + threadIdx.x;
    #pragma unroll
    for (int s = 0; s < 5; s++) {
        if (idx >= cfg.base[s] && idx < cfg.base[s+1]) {
            int li = idx - cfg.base[s];
            int Cin = cfg.Cin[s], ntaps = cfg.ntaps[s];
            int bi = li >> 13;           // 8192 elems per stage block
            int r = li & 8191;
            int co = r >> 5, cil = r & 31;
            int nch = Cin >> 5;
            int t = bi / nch, cc = bi - t*nch;
            int ci = cc*32 + cil;
            float v = cfg.src[s][((size_t)co*Cin + ci)*ntaps + t];
            cfg.dh[s][li] = __float2half(v);
            return;
        }
    }
}

__global__ void z0_kernel(const float* __restrict__ w_gp, const float* __restrict__ gpv, float* __restrict__ z0)
{
    __shared__ float red[256];
    int co = blockIdx.x, b = blockIdx.y;
    float s = 0.f;
    for (int ci = threadIdx.x; ci < CINC; ci += 256)
        s += w_gp[(size_t)co*CINC + ci] * gpv[b*CINC + ci];
    red[threadIdx.x] = s; __syncthreads();
    for (int o = 128; o > 0; o >>= 1) { if (threadIdx.x < o) red[threadIdx.x] += red[threadIdx.x + o]; __syncthreads(); }
    if (threadIdx.x == 0) z0[b*INNERC + co] = red[0];
}

__global__ void bn0_kernel(const float* __restrict__ z0, const float* __restrict__ g,
                           const float* __restrict__ bb, float* __restrict__ br0)
{
    int c = threadIdx.x;
    float m = 0.f;
    for (int b = 0; b < 4; b++) m += z0[b*INNERC + c];
    m *= 0.25f;
    float v = 0.f;
    for (int b = 0; b < 4; b++) { float d = z0[b*INNERC + c] - m; v += d*d; }
    v *= 0.25f;
    float is = rsqrtf(v + 1e-5f);
    for (int b = 0; b < 4; b++) {
        float val = g[c]*(z0[b*INNERC + c] - m)*is + bb[c];
        br0[b*INNERC + c] = fmaxf(val, 0.f);
    }
}

// ------------------------- mma.sync conv kernel -------------------------
// CTA: 128 pixels x 128 co, 8 warps (4x2), warp 32x64, pure fp16, fp32 accum
// K-chunk 32, stage = 16KB (A 8K | B 8K), 4-deep ring, wait_group 2, 3 CTAs/SM.
// Fully-OOB tap stages skipped (compacted valid-stage sequence).
#define STAGE_BYTES 16384u

template<typename OutT>
__global__ __launch_bounds__(256, 3)
void mma_conv_kernel(const __half* __restrict__ Ahp,
                     ConvCfg cfg, OutT* __restrict__ outbuf, int Cin, int outStride)
{
    extern __shared__ char smem[];
    const uint32_t sbase = smem_u32(smem);
    const int tid = threadIdx.x;
    const int wid = tid >> 5, lane = tid & 31;
    const int branch = blockIdx.z >> 2;
    const int b = blockIdx.z & 3;
    const __half* Bhp = cfg.wh[branch];
    const int ntaps = cfg.ntaps[branch];
    const int dil = cfg.dil[branch];
    const int outOff = cfg.off[branch];
    const int p0 = blockIdx.y * 128;
    const int co0 = blockIdx.x * 128;
    const int nchunk = Cin >> 5;
    const int nstage = ntaps * nchunk;

    const int h_lo = p0 / HH;
    const int h_hi = (p0 + 127 < HP ? p0 + 127 : HP - 1) / HH;

    auto skipstage = [&](int i) -> bool {
        if (ntaps != 9) return false;
        int t = i / nchunk;
        int dh = (t/3 - 1) * dil;
        return (h_hi + dh < 0) || (h_lo + dh > HH - 1);
    };
    auto nextv = [&](int i) -> int {
        while (i < nstage && skipstage(i)) ++i;
        return i;
    };

    // loader role: tid 0-127 load A rows, tid 128-255 load B rows (64B each)
    const int isB = tid >> 7;
    const int lrow = tid & 127;

    const int pA = p0 + lrow;
    const int hA = pA / HH, wA = pA - hA*HH;

    uint32_t soff[4];
    #pragma unroll
    for (int j = 0; j < 4; j++)
        soff[j] = sw64((uint32_t)lrow*64u + j*16u) + (uint32_t)isB*8192u;

    auto issue = [&](int i, int buf) {
        int t = i / nchunk;
        int cc = i - t*nchunk;
        uint32_t sb = sbase + (uint32_t)buf * STAGE_BYTES;
        if (!isB) {
            int c0 = cc << 5;
            int dh = (ntaps == 9) ? (t/3 - 1)*dil : 0;
            int dw = (ntaps == 9) ? (t - (t/3)*3 - 1)*dil : 0;
            int hh = hA + dh, ww = wA + dw;
            bool ok = (pA < HP) && (hh >= 0) && (hh < HH) && (ww >= 0) && (ww < HH);
            const char* asrc = (const char*)(Ahp + ((size_t)(b*HP + (ok ? (hh*HH + ww) : 0)))*Cin + c0);
            int sz = ok ? 16 : 0;
            #pragma unroll
            for (int j = 0; j < 4; j++)
                cp16(sb + soff[j], asrc + j*16, sz);
        } else {
            const char* bsrc = (const char*)(Bhp + (size_t)i*8192 + (size_t)(co0 + lrow)*32);
            #pragma unroll
            for (int j = 0; j < 4; j++)
                cp16(sb + soff[j], bsrc + j*16, 16);
        }
    };

    const int wm = wid >> 1;
    const int wn = wid & 1;
    const int ar = lane & 15;
    const int acolsel = (lane >> 4) << 4;
    const int br = (lane & 7) + ((lane >> 4) << 3);
    const int bcolsel = (lane & 8) ? 16 : 0;

    float acc[2][8][4];
    #pragma unroll
    for (int m = 0; m < 2; m++)
        #pragma unroll
        for (int j = 0; j < 8; j++)
            #pragma unroll
            for (int e = 0; e < 4; e++) acc[m][j][e] = 0.f;

    // compacted valid-stage pipeline with 3 stages of look-ahead (4-deep ring)
    int s0 = nextv(0);
    int s1 = (s0 < nstage) ? nextv(s0 + 1) : nstage;
    int s2 = (s1 < nstage) ? nextv(s1 + 1) : nstage;
    int s3 = (s2 < nstage) ? nextv(s2 + 1) : nstage;

    issue(s0, 0); CP_COMMIT();
    if (s1 < nstage) issue(s1, 1);
    CP_COMMIT();
    if (s2 < nstage) issue(s2, 2);
    CP_COMMIT();

    int bi = 0;
    while (s0 < nstage) {
        CP_WAIT2();            // pending {bi,bi+1,bi+2} -> group bi complete
        __syncthreads();       // visibility + protects ring reuse
        if (s3 < nstage) issue(s3, (bi + 3) & 3);
        CP_COMMIT();

        uint32_t sb = sbase + (uint32_t)(bi & 3) * STAGE_BYTES;
        #pragma unroll
        for (int ks = 0; ks < 2; ks++) {
            uint32_t a_h[2][4];
            #pragma unroll
            for (int m = 0; m < 2; m++) {
                uint32_t off = sw64((uint32_t)(wm*32 + m*16 + ar)*64u + (uint32_t)(ks*32 + acolsel));
                ldsm4(a_h[m], sb + off);
            }
            #pragma unroll
            for (int nb = 0; nb < 4; nb++) {
                uint32_t offb = sw64((uint32_t)(wn*64 + nb*16 + br)*64u + (uint32_t)(ks*32 + bcolsel));
                uint32_t b_h[4];
                ldsm4(b_h, sb + 8192u + offb);
                #pragma unroll
                for (int m = 0; m < 2; m++)
                    #pragma unroll
                    for (int h2 = 0; h2 < 2; h2++) {
                        mma16816(acc[m][nb*2 + h2], a_h[m], b_h[h2*2], b_h[h2*2 + 1]);
                    }
            }
        }

        s0 = s1; s1 = s2; s2 = s3;
        s3 = (s3 < nstage) ? nextv(s3 + 1) : nstage;
        bi++;
    }

    #pragma unroll
    for (int m = 0; m < 2; m++) {
        #pragma unroll
        for (int e2 = 0; e2 < 2; e2++) {
            int p = p0 + wm*32 + m*16 + (lane >> 2) + e2*8;
            if (p >= HP) continue;
            OutT* orow = outbuf + ((size_t)b*HP + p)*outStride + outOff + co0 + wn*64 + 2*(lane & 3);
            #pragma unroll
            for (int j = 0; j < 8; j++)
                store2(orow + j*8, acc[m][j][e2*2], acc[m][j][e2*2 + 1]);
        }
    }
}

// ------------------------- BN / epilogue kernels -------------------------
template<typename T>
__global__ void stats_partial_kernel(const T* __restrict__ buf, int rows, int cstride, int coff,
                                     int nch, float* __restrict__ psum, float* __restrict__ psq)
{
    int slice = blockIdx.x;
    int r0 = (int)((long long)rows * slice / NSLICE);
    int r1 = (int)((long long)rows * (slice + 1) / NSLICE);
    for (int c = threadIdx.x; c < nch; c += 256) {
        float s = 0.f, q = 0.f;
        for (int r = r0; r < r1; ++r) {
            float v = ldf(&buf[(size_t)r*cstride + coff + c]);
            s += v; q += v*v;
        }
        psum[(size_t)slice*nch + c] = s;
        psq [(size_t)slice*nch + c] = q;
    }
}

__global__ void stats_final_kernel(const float* __restrict__ psum, const float* __restrict__ psq,
                                   int nch, int rows, float* __restrict__ mean, float* __restrict__ invstd)
{
    int c = blockIdx.x * 256 + threadIdx.x;
    if (c >= nch) return;
    float s = 0.f, q = 0.f;
    for (int i = 0; i < NSLICE; i++) { s += psum[(size_t)i*nch + c]; q += psq[(size_t)i*nch + c]; }
    float m = s / (float)rows;
    float v = q / (float)rows - m*m;
    mean[c] = m;
    invstd[c] = rsqrtf(v + 1e-5f);
}

// aspp_rawh (fp16, 1024ch) + br0 -> fp16 concat plane (1280ch) with BN+ReLU
__global__ __launch_bounds__(256)
void bn_apply_aspp_kernel(const __half* __restrict__ raw, const float* __restrict__ br0,
    const float* __restrict__ mean, const float* __restrict__ invstd,
    const float* __restrict__ g1, const float* __restrict__ b1,
    const float* __restrict__ g2, const float* __restrict__ b2,
    const float* __restrict__ g3, const float* __restrict__ b3,
    const float* __restrict__ g4, const float* __restrict__ b4,
    __half* __restrict__ oh)
{
    const int cb = blockIdx.y;            // 0..4 channel block of 256
    const int c = threadIdx.x;
    const int bp0 = blockIdx.x * 8;
    if (cb == 0) {
        #pragma unroll
        for (int i = 0; i < 8; i++) {
            int bp = bp0 + i;
            if (bp >= ROWS) break;
            int b = bp / HP;
            oh[(size_t)bp*NCAT + c] = __float2half(br0[b*INNERC + c]);
        }
        return;
    }
    const int ch = (cb - 1)*256 + c;
    const float* g; const float* bb;
    if (cb == 1)      { g = g1; bb = b1; }
    else if (cb == 2) { g = g2; bb = b2; }
    else if (cb == 3) { g = g3; bb = b3; }
    else              { g = g4; bb = b4; }
    const float gm = g[c]*invstd[ch];
    const float bt = bb[c] - mean[ch]*gm;
    #pragma unroll
    for (int i = 0; i < 8; i++) {
        int bp = bp0 + i;
        if (bp >= ROWS) break;
        float v = fmaxf(gm*__half2float(raw[(size_t)bp*1024 + ch]) + bt, 0.f);
        oh[(size_t)bp*NCAT + cb*256 + c] = __float2half(v);
    }
}

// classifier + argmax with fused BN affine+ReLU on raw fea
__global__ __launch_bounds__(128)
void final_conv_kernel(const float* __restrict__ fea, const float* __restrict__ w_fin,
                       const float* __restrict__ b_fin,
                       const float* __restrict__ mean, const float* __restrict__ invstd,
                       const float* __restrict__ g, const float* __restrict__ bb,
                       float* __restrict__ res, int* __restrict__ pred)
{
    __shared__ float ws[NCCL*INNERC];
    __shared__ float bs[NCCL];
    __shared__ float gm[INNERC];
    __shared__ float bt[INNERC];
    for (int i = threadIdx.x; i < NCCL*INNERC; i += 128) ws[i] = w_fin[i];
    if (threadIdx.x < NCCL) bs[threadIdx.x] = b_fin[threadIdx.x];
    for (int i = threadIdx.x; i < INNERC; i += 128) {
        float gmv = g[i]*invstd[i];
        gm[i] = gmv;
        bt[i] = bb[i] - mean[i]*gmv;
    }
    __syncthreads();
    int gp = blockIdx.x * 128 + threadIdx.x;
    if (gp >= ROWS) return;
    int b = gp / HP, p = gp % HP;
    const float* f = fea + (size_t)gp * INNERC;
    float acc[NCCL];
    #pragma unroll
    for (int k = 0; k < NCCL; k++) acc[k] = bs[k];
    for (int c = 0; c < INNERC; c += 4) {
        float4 v = *(const float4*)(f + c);
        v.x = fmaxf(gm[c  ]*v.x + bt[c  ], 0.f);
        v.y = fmaxf(gm[c+1]*v.y + bt[c+1], 0.f);
        v.z = fmaxf(gm[c+2]*v.z + bt[c+2], 0.f);
        v.w = fmaxf(gm[c+3]*v.w + bt[c+3], 0.f);
        #pragma unroll
        for (int k = 0; k < NCCL; k++) {
            acc[k] += v.x*ws[k*INNERC + c] + v.y*ws[k*INNERC + c + 1]
                    + v.z*ws[k*INNERC + c + 2] + v.w*ws[k*INNERC + c + 3];
        }
    }
    int best = 0; float bv = acc[0];
    #pragma unroll
    for (int k = 1; k < NCCL; k++) if (acc[k] > bv) { bv = acc[k]; best = k; }
    #pragma unroll
    for (int k = 0; k < NCCL; k++) res[((size_t)(b*NCCL + k))*HP + p] = acc[k];
    pred[gp] = best;
}

// per-class masked sums with fused BN affine+ReLU on raw fea
__global__ __launch_bounds__(256)
void region_partial_kernel(const float* __restrict__ fea, const int* __restrict__ pred,
                           const float* __restrict__ mean, const float* __restrict__ invstd,
                           const float* __restrict__ g, const float* __restrict__ bb,
                           float* __restrict__ psum, float* __restrict__ pcnt)
{
    __shared__ float acc[NCCL*INNERC];
    __shared__ float cnt[NCCL];
    int tid = threadIdx.x;
    for (int i = tid; i < NCCL*INNERC; i += 256) acc[i] = 0.f;
    if (tid < NCCL) cnt[tid] = 0.f;
    const float gmv = g[tid]*invstd[tid];
    const float btv = bb[tid] - mean[tid]*gmv;
    __syncthreads();
    int slice = blockIdx.x;
    int r0 = (int)((long long)ROWS * slice / RSLICE);
    int r1 = (int)((long long)ROWS * (slice + 1) / RSLICE);
    for (int r = r0; r < r1; ++r) {
        int k = pred[r];
        float v = fmaxf(gmv*fea[(size_t)r*INNERC + tid] + btv, 0.f);
        acc[k*INNERC + tid] += v;
        if (tid == 0) cnt[k] += 1.f;
    }
    __syncthreads();
    for (int i = tid; i < NCCL*INNERC; i += 256) psum[(size_t)slice*NCCL*INNERC + i] = acc[i];
    if (tid < NCCL) pcnt[slice*NCCL + tid] = cnt[tid];
}

__global__ void region_final_kernel(const float* __restrict__ psum, const float* __restrict__ pcnt,
                                    float* __restrict__ keys, float* __restrict__ counts)
{
    __shared__ float red[256];
    __shared__ float cs;
    int k = blockIdx.x, tid = threadIdx.x;
    float s = 0.f;
    for (int i = 0; i < RSLICE; i++) s += psum[(size_t)i*NCCL*INNERC + k*INNERC + tid];
    if (tid == 0) {
        float c = 0.f;
        for (int i = 0; i < RSLICE; i++) c += pcnt[i*NCCL + k];
        counts[k] = c; cs = c;
    }
    __syncthreads();
    float c = cs;
    float key = s / fmaxf(c, 1.f);
    red[tid] = key*key; __syncthreads();
    for (int o = 128; o > 0; o >>= 1) { if (tid < o) red[tid] += red[tid + o]; __syncthreads(); }
    float nrm = sqrtf(red[0]);
    keys[k*INNERC + tid] = key / fmaxf(nrm, 1e-12f);
}

__global__ __launch_bounds__(128)
void sims_kernel(const float* __restrict__ keys, const float* __restrict__ queues,
                 float* __restrict__ psume, float* __restrict__ adiag)
{
    __shared__ float ks[NCCL*INNERC];
    __shared__ float red[128];
    int tid = threadIdx.x;
    for (int i = tid; i < NCCL*INNERC; i += 128) ks[i] = keys[i];
    __syncthreads();
    int j = blockIdx.y, lc = blockIdx.x;
    int l = lc*LCHUNK + tid;
    float acc[NCCL];
    #pragma unroll
    for (int k = 0; k < NCCL; k++) acc[k] = 0.f;
    if (l < QLL) {
        const float* q = queues + (size_t)j*INNERC*QLL + l;
        #pragma unroll 4
        for (int c = 0; c < INNERC; ++c) {
            float qv = q[(size_t)c*QLL];
            #pragma unroll
            for (int k = 0; k < NCCL; k++) acc[k] += ks[k*INNERC + c]*qv;
        }
    }
    const float scale = 1.f/((float)INNERC*0.2f);
    for (int k = 0; k < NCCL; k++) {
        float a = acc[k]*scale;
        if (j == k && l < QLL) adiag[k*QLL + l] = a;
        red[tid] = (l < QLL) ? expf(a) : 0.f;
        __syncthreads();
        for (int o = 64; o > 0; o >>= 1) { if (tid < o) red[tid] += red[tid + o]; __syncthreads(); }
        if (tid == 0) psume[((size_t)k*NCCL + j)*NLCH + lc] = red[0];
        __syncthreads();
    }
}

// merged: lneg + per-class loss + final sum, one block of 256 threads
__global__ __launch_bounds__(256)
void loss_kernel(const float* __restrict__ psume, const float* __restrict__ adiag,
                 const float* __restrict__ counts, float* __restrict__ out, int idx)
{
    __shared__ float red[256];
    __shared__ float lneg[NCCL];
    int tid = threadIdx.x;
    if (tid < NCCL) {
        int k = tid;
        float tot = 0.f;
        for (int j = 0; j < NCCL; j++) {
            if (j == k) continue;
            for (int lc = 0; lc < NLCH; lc++) tot += psume[((size_t)k*NCCL + j)*NLCH + lc];
        }
        lneg[k] = logf(tot);
    }
    __syncthreads();
    float total = 0.f;   // accumulated on tid 0 across classes
    for (int k = 0; k < NCCL; k++) {
        float L = lneg[k];
        float s = 0.f;
        for (int l = tid; l < QLL; l += 256)
            s += log1pf(expf(L - adiag[k*QLL + l]));
        red[tid] = s; __syncthreads();
        for (int o = 128; o > 0; o >>= 1) { if (tid < o) red[tid] += red[tid + o]; __syncthreads(); }
        if (tid == 0 && counts[k] > 0.f) total += red[0]/(float)QLL;
        __syncthreads();
    }
    if (tid == 0) out[idx] = total;
}

// ------------------------- launch -------------------------
static float* sym_f(const void* s) { void* p = nullptr; cudaGetSymbolAddress(&p, s); return (float*)p; }
static __half* sym_h(const void* s) { void* p = nullptr; cudaGetSymbolAddress(&p, s); return (__half*)p; }

#define CONV_SMEM (4*16384)

extern "C" void kernel_launch(void* const* d_in, const int* in_sizes, int n_in,
                              void* d_out, int out_size)
{
    const float* x      = (const float*)d_in[0];
    const float* w_gp   = (const float*)d_in[1];
    const float* gg_gp  = (const float*)d_in[2];
    const float* gb_gp  = (const float*)d_in[3];
    const float* w_1x1  = (const float*)d_in[4];
    const float* ga_1   = (const float*)d_in[5];
    const float* gb_1   = (const float*)d_in[6];
    const float* w_d12  = (const float*)d_in[7];
    const float* ga_12  = (const float*)d_in[8];
    const float* gb_12  = (const float*)d_in[9];
    const float* w_d24  = (const float*)d_in[10];
    const float* ga_24  = (const float*)d_in[11];
    const float* gb_24  = (const float*)d_in[12];
    const float* w_d36  = (const float*)d_in[13];
    const float* ga_36  = (const float*)d_in[14];
    const float* gb_36  = (const float*)d_in[15];
    const float* w_head = (const float*)d_in[16];
    const float* ga_h   = (const float*)d_in[17];
    const float* gb_h   = (const float*)d_in[18];
    const float* w_fin  = (const float*)d_in[19];
    const float* b_fin  = (const float*)d_in[20];
    const float* queues = (const float*)d_in[21];
    float* out = (float*)d_out;

    __half* xh   = sym_h(sc_xh);
    __half* aspp_rawh = sym_h(sc_aspp_rawh);
    __half* aH   = sym_h(sc_asppH);
    float* fea   = sym_f(sc_fea);
    __half *w1h = sym_h(sc_w1h);
    __half *w12h = sym_h(sc_w12h);
    __half *w24h = sym_h(sc_w24h);
    __half *w36h = sym_h(sc_w36h);
    __half *whh = sym_h(sc_whh);
    float* gpp    = sym_f(sc_gpp);
    float* gpv    = sym_f(sc_gpv);
    float* z0     = sym_f(sc_z0);
    float* br0    = sym_f(sc_br0);
    float* psum   = sym_f(sc_psum);
    float* psq    = sym_f(sc_psq);
    float* meanv  = sym_f(sc_mean);
    float* invstd = sym_f(sc_invstd);
    float* mean2  = sym_f(sc_mean2);
    float* invstd2= sym_f(sc_invstd2);
    int*   pred;  { void* p = nullptr; cudaGetSymbolAddress(&p, sc_pred); pred = (int*)p; }
    float* rpsum  = sym_f(sc_rpsum);
    float* rpcnt  = sym_f(sc_rpcnt);
    float* keys   = sym_f(sc_keys);
    float* counts = sym_f(sc_counts);
    float* psume  = sym_f(sc_psume);
    float* adiag  = sym_f(sc_adiag);

    static int smem_set = 0;
    if (!smem_set) {
        cudaFuncSetAttribute(mma_conv_kernel<__half>, cudaFuncAttributeMaxDynamicSharedMemorySize, CONV_SMEM);
        cudaFuncSetAttribute(mma_conv_kernel<float>, cudaFuncAttributeMaxDynamicSharedMemorySize, CONV_SMEM);
        smem_set = 1;
    }

    // 1. input transpose + gp partials
    transpose_x_fp16_kernel<<<dim3(NPB, CINC/32, BATCH), dim3(32,8)>>>(x, xh, gpp);
    gp_final_kernel<<<(BATCH*CINC + 255)/256, 256>>>(gpp, gpv);

    // 2. all weight transforms in one launch (fp16, 32-ci stage blocks)
    {
        WtCfg wc;
        wc.src[0] = w_1x1;  wc.dh[0] = w1h;  wc.Cin[0] = CINC; wc.ntaps[0] = 1;
        wc.src[1] = w_d12;  wc.dh[1] = w12h; wc.Cin[1] = CINC; wc.ntaps[1] = 9;
        wc.src[2] = w_d24;  wc.dh[2] = w24h; wc.Cin[2] = CINC; wc.ntaps[2] = 9;
        wc.src[3] = w_d36;  wc.dh[3] = w36h; wc.Cin[3] = CINC; wc.ntaps[3] = 9;
        wc.src[4] = w_head; wc.dh[4] = whh;  wc.Cin[4] = NCAT; wc.ntaps[4] = 9;
        int acc = 0;
        for (int s = 0; s < 5; s++) { wc.base[s] = acc; acc += wc.ntaps[s]*wc.Cin[s]*INNERC; }
        wc.base[5] = acc;
        wtrans_all_kernel<<<(acc + 255)/256, 256>>>(wc);
    }

    // 3. global-pool branch
    z0_kernel<<<dim3(INNERC, BATCH), 256>>>(w_gp, gpv, z0);
    bn0_kernel<<<1, 256>>>(z0, gg_gp, gb_gp, br0);

    // 4. all four ASPP convs in ONE fused launch -> fp16 pre-BN buffer
    {
        ConvCfg cfg;
        cfg.wh[0] = w1h;  cfg.ntaps[0] = 1; cfg.dil[0] = 0;  cfg.off[0] = 0;
        cfg.wh[1] = w12h; cfg.ntaps[1] = 9; cfg.dil[1] = 12; cfg.off[1] = 256;
        cfg.wh[2] = w24h; cfg.ntaps[2] = 9; cfg.dil[2] = 24; cfg.off[2] = 512;
        cfg.wh[3] = w36h; cfg.ntaps[3] = 9; cfg.dil[3] = 36; cfg.off[3] = 768;
        dim3 grid(2, (HP + 127)/128, 4*BATCH);
        mma_conv_kernel<__half><<<grid, 256, CONV_SMEM>>>(xh, cfg, aspp_rawh, CINC, 1024);
    }

    // 5. BN + ReLU + concat -> fp16 plane
    stats_partial_kernel<__half><<<NSLICE, 256>>>(aspp_rawh, ROWS, 1024, 0, 1024, psum, psq);
    stats_final_kernel<<<4, 256>>>(psum, psq, 1024, ROWS, meanv, invstd);
    bn_apply_aspp_kernel<<<dim3((ROWS + 7)/8, 5), 256>>>(aspp_rawh, br0, meanv, invstd,
        ga_1, gb_1, ga_12, gb_12, ga_24, gb_24, ga_36, gb_36, aH);

    // 6. head conv (raw fp32 out) + BN stats (BN-apply fused into consumers)
    {
        ConvCfg cfg;
        cfg.wh[0] = whh; cfg.ntaps[0] = 9; cfg.dil[0] = 1; cfg.off[0] = 0;
        cfg.wh[1] = whh; cfg.ntaps[1] = 9; cfg.dil[1] = 1; cfg.off[1] = 0;
        cfg.wh[2] = whh; cfg.ntaps[2] = 9; cfg.dil[2] = 1; cfg.off[2] = 0;
        cfg.wh[3] = whh; cfg.ntaps[3] = 9; cfg.dil[3] = 1; cfg.off[3] = 0;
        dim3 grid(2, (HP + 127)/128, BATCH);
        mma_conv_kernel<float><<<grid, 256, CONV_SMEM>>>(aH, cfg, fea, NCAT, INNERC);
    }
    stats_partial_kernel<float><<<NSLICE, 256>>>(fea, ROWS, INNERC, 0, INNERC, psum, psq);
    stats_final_kernel<<<1, 256>>>(psum, psq, INNERC, ROWS, mean2, invstd2);

    // 7. classifier + argmax (BN affine fused; res straight to d_out)
    final_conv_kernel<<<(ROWS + 127)/128, 128>>>(fea, w_fin, b_fin,
                                                 mean2, invstd2, ga_h, gb_h, out, pred);

    // 8. region keys (BN affine fused)
    region_partial_kernel<<<RSLICE, 256>>>(fea, pred, mean2, invstd2, ga_h, gb_h, rpsum, rpcnt);
    region_final_kernel<<<NCCL, 256>>>(rpsum, rpcnt, keys, counts);

    // 9. contrast loss
    sims_kernel<<<dim3(NLCH, NCCL), 128>>>(keys, queues, psume, adiag);
    loss_kernel<<<1, 256>>>(psume, adiag, counts, out, out_size - 1);
}

// round 13
// speedup vs baseline: 1.4414x; 1.4414x over previous
#include <cuda_runtime.h>
#include <cuda_fp16.h>
#include <math.h>
#include <stdint.h>

#define BATCH 4
#define CINC 2048
#define HH 65
#define HP (HH*HH)          // 4225
#define INNERC 256
#define NCAT 1280
#define NCCL 19
#define QLL 2975
#define ROWS (BATCH*HP)     // 16900
#define NSLICE 512
#define RSLICE 64
#define LCHUNK 128
#define NLCH 24             // ceil(2975/128)
#define NPB 133             // ceil(HP/32) pixel blocks for gp partials

// ------------------------- static scratch (no allocation allowed) -------------------------
static __device__ __half sc_xh[(size_t)BATCH*HP*CINC];
static __device__ __half sc_aspp_rawh[(size_t)BATCH*HP*1024];    // pre-BN conv branches, fp16
static __device__ __half sc_asppH[(size_t)BATCH*HP*NCAT];
static __device__ float sc_fea[(size_t)BATCH*HP*INNERC];         // pre-BN head conv out
// blocked fp16 weights: [stage=(t,cc32)][256 co][32 ci]
static __device__ __half sc_w1h[CINC*INNERC];
static __device__ __half sc_w12h[9*CINC*INNERC];
static __device__ __half sc_w24h[9*CINC*INNERC];
static __device__ __half sc_w36h[9*CINC*INNERC];
static __device__ __half sc_whh[9*NCAT*INNERC];
static __device__ float sc_gpp[BATCH*NPB*CINC];              // gp partial sums
static __device__ float sc_gpv[BATCH*CINC];
static __device__ float sc_z0[BATCH*INNERC];
static __device__ float sc_br0[BATCH*INNERC];
static __device__ float sc_psum[NSLICE*1024];
static __device__ float sc_psq[NSLICE*1024];
static __device__ float sc_mean[1024];
static __device__ float sc_invstd[1024];
static __device__ float sc_mean2[INNERC];
static __device__ float sc_invstd2[INNERC];
static __device__ int   sc_pred[ROWS];
static __device__ float sc_rpsum[RSLICE*NCCL*INNERC];
static __device__ float sc_rpcnt[RSLICE*NCCL];
static __device__ float sc_keys[NCCL*INNERC];
static __device__ float sc_counts[NCCL];
static __device__ float sc_psume[NCCL*NCCL*NLCH];
static __device__ float sc_adiag[NCCL*QLL];

// ------------------------- helpers -------------------------
__device__ __forceinline__ uint32_t smem_u32(const void* p) {
    uint32_t a;
    asm("{ .reg .u64 t; cvta.to.shared.u64 t, %1; cvt.u32.u64 %0, t; }" : "=r"(a) : "l"(p));
    return a;
}
// 64B-row swizzle: XOR row bits (1,2) into 16B-granule bits
__device__ __forceinline__ uint32_t sw64(uint32_t off) { return off ^ ((off >> 3) & 0x30); }

__device__ __forceinline__ void cp16(uint32_t dst, const void* src, int sz) {
    asm volatile("cp.async.cg.shared.global [%0], [%1], 16, %2;"
                 :: "r"(dst), "l"(src), "r"(sz) : "memory");
}
#define CP_COMMIT() asm volatile("cp.async.commit_group;" ::: "memory")
#define CP_WAIT2()  asm volatile("cp.async.wait_group 2;" ::: "memory")

__device__ __forceinline__ void ldsm4(uint32_t* r, uint32_t addr) {
    asm volatile("ldmatrix.sync.aligned.m8n8.x4.shared.b16 {%0,%1,%2,%3}, [%4];"
                 : "=r"(r[0]), "=r"(r[1]), "=r"(r[2]), "=r"(r[3]) : "r"(addr));
}
__device__ __forceinline__ void mma16816(float* d, const uint32_t* a, uint32_t b0, uint32_t b1) {
    asm volatile("mma.sync.aligned.m16n8k16.row.col.f32.f16.f16.f32 "
                 "{%0,%1,%2,%3}, {%4,%5,%6,%7}, {%8,%9}, {%0,%1,%2,%3};"
                 : "+f"(d[0]), "+f"(d[1]), "+f"(d[2]), "+f"(d[3])
                 : "r"(a[0]), "r"(a[1]), "r"(a[2]), "r"(a[3]), "r"(b0), "r"(b1));
}
__device__ __forceinline__ void store2(float* p, float a, float b) { *(float2*)p = make_float2(a, b); }
__device__ __forceinline__ void store2(__half* p, float a, float b) { *(__half2*)p = __floats2half2_rn(a, b); }
__device__ __forceinline__ float ldf(const float* p) { return *p; }
__device__ __forceinline__ float ldf(const __half* p) { return __half2float(*p); }

struct ConvCfg {
    const __half* wh[4];
    int ntaps[4];
    int dil[4];
    int off[4];
};
struct WtCfg {
    const float* src[5];
    __half* dh[5];
    int Cin[5];
    int ntaps[5];
    int base[6];
};

// ------------------------- pre kernels -------------------------

// NCHW -> [b][p][ci] fp16 + global-pool partial sums
__global__ void transpose_x_fp16_kernel(const float* __restrict__ x,
                                        __half* __restrict__ xh, float* __restrict__ gpp)
{
    __shared__ float tile[32][33];
    __shared__ float red[32][8];
    int b = blockIdx.z;
    int p0 = blockIdx.x * 32, c0 = blockIdx.y * 32;
    int tx = threadIdx.x, ty = threadIdx.y; // 32 x 8
    #pragma unroll
    for (int i = 0; i < 32; i += 8) {
        int c = c0 + ty + i, p = p0 + tx;
        tile[ty + i][tx] = (p < HP) ? x[((size_t)b*CINC + c)*HP + p] : 0.f;
    }
    __syncthreads();
    #pragma unroll
    for (int i = 0; i < 32; i += 8) {
        int p = p0 + ty + i, c = c0 + tx;
        if (p < HP)
            xh[((size_t)b*HP + p)*CINC + c] = __float2half(tile[tx][ty + i]);
    }
    {
        float s = 0.f;
        #pragma unroll
        for (int j = 0; j < 4; j++) s += tile[tx][ty*4 + j];
        red[tx][ty] = s;
        __syncthreads();
        if (ty == 0) {
            float t = 0.f;
            #pragma unroll
            for (int k = 0; k < 8; k++) t += red[tx][k];
            gpp[((size_t)b*NPB + blockIdx.x)*CINC + c0 + tx] = t;
        }
    }
}

__global__ void gp_final_kernel(const float* __restrict__ gpp, float* __restrict__ gpv)
{
    int idx = blockIdx.x * 256 + threadIdx.x;   // (b,c)
    if (idx >= BATCH*CINC) return;
    int b = idx >> 11, c = idx & 2047;
    float s = 0.f;
    for (int k = 0; k < NPB; k++) s += gpp[((size_t)b*NPB + k)*CINC + c];
    gpv[idx] = s / (float)HP;
}

// all five weight transforms in one launch: w[co][ci][t] -> [stage=(t,cc32)][co 256][ci 32] fp16
__global__ void wtrans_all_kernel(WtCfg cfg)
{
    int idx = blockIdx.x * 256 + threadIdx.x;
    #pragma unroll
    for (int s = 0; s < 5; s++) {
        if (idx >= cfg.base[s] && idx < cfg.base[s+1]) {
            int li = idx - cfg.base[s];
            int Cin = cfg.Cin[s], ntaps = cfg.ntaps[s];
            int bi = li >> 13;           // 8192 elems per stage block
            int r = li & 8191;
            int co = r >> 5, cil = r & 31;
            int nch = Cin >> 5;
            int t = bi / nch, cc = bi - t*nch;
            int ci = cc*32 + cil;
            float v = cfg.src[s][((size_t)co*Cin + ci)*ntaps + t];
            cfg.dh[s][li] = __float2half(v);
            return;
        }
    }
}

__global__ void z0_kernel(const float* __restrict__ w_gp, const float* __restrict__ gpv, float* __restrict__ z0)
{
    __shared__ float red[256];
    int co = blockIdx.x, b = blockIdx.y;
    float s = 0.f;
    for (int ci = threadIdx.x; ci < CINC; ci += 256)
        s += w_gp[(size_t)co*CINC + ci] * gpv[b*CINC + ci];
    red[threadIdx.x] = s; __syncthreads();
    for (int o = 128; o > 0; o >>= 1) { if (threadIdx.x < o) red[threadIdx.x] += red[threadIdx.x + o]; __syncthreads(); }
    if (threadIdx.x == 0) z0[b*INNERC + co] = red[0];
}

__global__ void bn0_kernel(const float* __restrict__ z0, const float* __restrict__ g,
                           const float* __restrict__ bb, float* __restrict__ br0)
{
    int c = threadIdx.x;
    float m = 0.f;
    for (int b = 0; b < 4; b++) m += z0[b*INNERC + c];
    m *= 0.25f;
    float v = 0.f;
    for (int b = 0; b < 4; b++) { float d = z0[b*INNERC + c] - m; v += d*d; }
    v *= 0.25f;
    float is = rsqrtf(v + 1e-5f);
    for (int b = 0; b < 4; b++) {
        float val = g[c]*(z0[b*INNERC + c] - m)*is + bb[c];
        br0[b*INNERC + c] = fmaxf(val, 0.f);
    }
}

// ------------------------- mma.sync conv kernel -------------------------
// CTA: 128 pixels x 128 co, 8 warps (4x2), warp 32x64, pure fp16, fp32 accum
// K-chunk 32, stage = 16KB (A 8K | B 8K), 4-deep ring, wait_group 2, 2 CTAs/SM.
// Fully-OOB tap stages skipped (compacted valid-stage sequence).
#define STAGE_BYTES 16384u

template<typename OutT>
__global__ __launch_bounds__(256, 2)
void mma_conv_kernel(const __half* __restrict__ Ahp,
                     ConvCfg cfg, OutT* __restrict__ outbuf, int Cin, int outStride)
{
    extern __shared__ char smem[];
    const uint32_t sbase = smem_u32(smem);
    const int tid = threadIdx.x;
    const int wid = tid >> 5, lane = tid & 31;
    const int branch = blockIdx.z >> 2;
    const int b = blockIdx.z & 3;
    const __half* Bhp = cfg.wh[branch];
    const int ntaps = cfg.ntaps[branch];
    const int dil = cfg.dil[branch];
    const int outOff = cfg.off[branch];
    const int p0 = blockIdx.y * 128;
    const int co0 = blockIdx.x * 128;
    const int nchunk = Cin >> 5;
    const int nstage = ntaps * nchunk;

    const int h_lo = p0 / HH;
    const int h_hi = (p0 + 127 < HP ? p0 + 127 : HP - 1) / HH;

    auto skipstage = [&](int i) -> bool {
        if (ntaps != 9) return false;
        int t = i / nchunk;
        int dh = (t/3 - 1) * dil;
        return (h_hi + dh < 0) || (h_lo + dh > HH - 1);
    };
    auto nextv = [&](int i) -> int {
        while (i < nstage && skipstage(i)) ++i;
        return i;
    };

    // loader role: tid 0-127 load A rows, tid 128-255 load B rows (64B each)
    const int isB = tid >> 7;
    const int lrow = tid & 127;

    const int pA = p0 + lrow;
    const int hA = pA / HH, wA = pA - hA*HH;

    uint32_t soff[4];
    #pragma unroll
    for (int j = 0; j < 4; j++)
        soff[j] = sw64((uint32_t)lrow*64u + j*16u) + (uint32_t)isB*8192u;

    auto issue = [&](int i, int buf) {
        int t = i / nchunk;
        int cc = i - t*nchunk;
        uint32_t sb = sbase + (uint32_t)buf * STAGE_BYTES;
        if (!isB) {
            int c0 = cc << 5;
            int dh = (ntaps == 9) ? (t/3 - 1)*dil : 0;
            int dw = (ntaps == 9) ? (t - (t/3)*3 - 1)*dil : 0;
            int hh = hA + dh, ww = wA + dw;
            bool ok = (pA < HP) && (hh >= 0) && (hh < HH) && (ww >= 0) && (ww < HH);
            const char* asrc = (const char*)(Ahp + ((size_t)(b*HP + (ok ? (hh*HH + ww) : 0)))*Cin + c0);
            int sz = ok ? 16 : 0;
            #pragma unroll
            for (int j = 0; j < 4; j++)
                cp16(sb + soff[j], asrc + j*16, sz);
        } else {
            const char* bsrc = (const char*)(Bhp + (size_t)i*8192 + (size_t)(co0 + lrow)*32);
            #pragma unroll
            for (int j = 0; j < 4; j++)
                cp16(sb + soff[j], bsrc + j*16, 16);
        }
    };

    const int wm = wid >> 1;
    const int wn = wid & 1;
    const int ar = lane & 15;
    const int acolsel = (lane >> 4) << 4;
    const int br = (lane & 7) + ((lane >> 4) << 3);
    const int bcolsel = (lane & 8) ? 16 : 0;

    float acc[2][8][4];
    #pragma unroll
    for (int m = 0; m < 2; m++)
        #pragma unroll
        for (int j = 0; j < 8; j++)
            #pragma unroll
            for (int e = 0; e < 4; e++) acc[m][j][e] = 0.f;

    // compacted valid-stage pipeline with 3 stages of look-ahead (4-deep ring)
    int s0 = nextv(0);
    int s1 = (s0 < nstage) ? nextv(s0 + 1) : nstage;
    int s2 = (s1 < nstage) ? nextv(s1 + 1) : nstage;
    int s3 = (s2 < nstage) ? nextv(s2 + 1) : nstage;

    issue(s0, 0); CP_COMMIT();
    if (s1 < nstage) issue(s1, 1);
    CP_COMMIT();
    if (s2 < nstage) issue(s2, 2);
    CP_COMMIT();

    int bi = 0;
    while (s0 < nstage) {
        CP_WAIT2();            // pending {bi,bi+1,bi+2} -> group bi complete
        __syncthreads();       // visibility + protects ring reuse
        if (s3 < nstage) issue(s3, (bi + 3) & 3);
        CP_COMMIT();

        uint32_t sb = sbase + (uint32_t)(bi & 3) * STAGE_BYTES;
        #pragma unroll
        for (int ks = 0; ks < 2; ks++) {
            uint32_t a_h[2][4];
            #pragma unroll
            for (int m = 0; m < 2; m++) {
                uint32_t off = sw64((uint32_t)(wm*32 + m*16 + ar)*64u + (uint32_t)(ks*32 + acolsel));
                ldsm4(a_h[m], sb + off);
            }
            #pragma unroll
            for (int nb = 0; nb < 4; nb++) {
                uint32_t offb = sw64((uint32_t)(wn*64 + nb*16 + br)*64u + (uint32_t)(ks*32 + bcolsel));
                uint32_t b_h[4];
                ldsm4(b_h, sb + 8192u + offb);
                #pragma unroll
                for (int m = 0; m < 2; m++)
                    #pragma unroll
                    for (int h2 = 0; h2 < 2; h2++) {
                        mma16816(acc[m][nb*2 + h2], a_h[m], b_h[h2*2], b_h[h2*2 + 1]);
                    }
            }
        }

        s0 = s1; s1 = s2; s2 = s3;
        s3 = (s3 < nstage) ? nextv(s3 + 1) : nstage;
        bi++;
    }

    #pragma unroll
    for (int m = 0; m < 2; m++) {
        #pragma unroll
        for (int e2 = 0; e2 < 2; e2++) {
            int p = p0 + wm*32 + m*16 + (lane >> 2) + e2*8;
            if (p >= HP) continue;
            OutT* orow = outbuf + ((size_t)b*HP + p)*outStride + outOff + co0 + wn*64 + 2*(lane & 3);
            #pragma unroll
            for (int j = 0; j < 8; j++)
                store2(orow + j*8, acc[m][j][e2*2], acc[m][j][e2*2 + 1]);
        }
    }
}

// ------------------------- BN / epilogue kernels -------------------------
template<typename T>
__global__ void stats_partial_kernel(const T* __restrict__ buf, int rows, int cstride, int coff,
                                     int nch, float* __restrict__ psum, float* __restrict__ psq)
{
    int slice = blockIdx.x;
    int r0 = (int)((long long)rows * slice / NSLICE);
    int r1 = (int)((long long)rows * (slice + 1) / NSLICE);
    for (int c = threadIdx.x; c < nch; c += 256) {
        float s = 0.f, q = 0.f;
        for (int r = r0; r < r1; ++r) {
            float v = ldf(&buf[(size_t)r*cstride + coff + c]);
            s += v; q += v*v;
        }
        psum[(size_t)slice*nch + c] = s;
        psq [(size_t)slice*nch + c] = q;
    }
}

__global__ void stats_final_kernel(const float* __restrict__ psum, const float* __restrict__ psq,
                                   int nch, int rows, float* __restrict__ mean, float* __restrict__ invstd)
{
    int c = blockIdx.x * 256 + threadIdx.x;
    if (c >= nch) return;
    float s = 0.f, q = 0.f;
    for (int i = 0; i < NSLICE; i++) { s += psum[(size_t)i*nch + c]; q += psq[(size_t)i*nch + c]; }
    float m = s / (float)rows;
    float v = q / (float)rows - m*m;
    mean[c] = m;
    invstd[c] = rsqrtf(v + 1e-5f);
}

// aspp_rawh (fp16, 1024ch) + br0 -> fp16 concat plane (1280ch) with BN+ReLU
__global__ __launch_bounds__(256)
void bn_apply_aspp_kernel(const __half* __restrict__ raw, const float* __restrict__ br0,
    const float* __restrict__ mean, const float* __restrict__ invstd,
    const float* __restrict__ g1, const float* __restrict__ b1,
    const float* __restrict__ g2, const float* __restrict__ b2,
    const float* __restrict__ g3, const float* __restrict__ b3,
    const float* __restrict__ g4, const float* __restrict__ b4,
    __half* __restrict__ oh)
{
    const int cb = blockIdx.y;            // 0..4 channel block of 256
    const int c = threadIdx.x;
    const int bp0 = blockIdx.x * 8;
    if (cb == 0) {
        #pragma unroll
        for (int i = 0; i < 8; i++) {
            int bp = bp0 + i;
            if (bp >= ROWS) break;
            int b = bp / HP;
            oh[(size_t)bp*NCAT + c] = __float2half(br0[b*INNERC + c]);
        }
        return;
    }
    const int ch = (cb - 1)*256 + c;
    const float* g; const float* bb;
    if (cb == 1)      { g = g1; bb = b1; }
    else if (cb == 2) { g = g2; bb = b2; }
    else if (cb == 3) { g = g3; bb = b3; }
    else              { g = g4; bb = b4; }
    const float gm = g[c]*invstd[ch];
    const float bt = bb[c] - mean[ch]*gm;
    #pragma unroll
    for (int i = 0; i < 8; i++) {
        int bp = bp0 + i;
        if (bp >= ROWS) break;
        float v = fmaxf(gm*__half2float(raw[(size_t)bp*1024 + ch]) + bt, 0.f);
        oh[(size_t)bp*NCAT + cb*256 + c] = __float2half(v);
    }
}

// classifier + argmax with fused BN affine+ReLU on raw fea
__global__ __launch_bounds__(128)
void final_conv_kernel(const float* __restrict__ fea, const float* __restrict__ w_fin,
                       const float* __restrict__ b_fin,
                       const float* __restrict__ mean, const float* __restrict__ invstd,
                       const float* __restrict__ g, const float* __restrict__ bb,
                       float* __restrict__ res, int* __restrict__ pred)
{
    __shared__ float ws[NCCL*INNERC];
    __shared__ float bs[NCCL];
    __shared__ float gm[INNERC];
    __shared__ float bt[INNERC];
    for (int i = threadIdx.x; i < NCCL*INNERC; i += 128) ws[i] = w_fin[i];
    if (threadIdx.x < NCCL) bs[threadIdx.x] = b_fin[threadIdx.x];
    for (int i = threadIdx.x; i < INNERC; i += 128) {
        float gmv = g[i]*invstd[i];
        gm[i] = gmv;
        bt[i] = bb[i] - mean[i]*gmv;
    }
    __syncthreads();
    int gp = blockIdx.x * 128 + threadIdx.x;
    if (gp >= ROWS) return;
    int b = gp / HP, p = gp % HP;
    const float* f = fea + (size_t)gp * INNERC;
    float acc[NCCL];
    #pragma unroll
    for (int k = 0; k < NCCL; k++) acc[k] = bs[k];
    for (int c = 0; c < INNERC; c += 4) {
        float4 v = *(const float4*)(f + c);
        v.x = fmaxf(gm[c  ]*v.x + bt[c  ], 0.f);
        v.y = fmaxf(gm[c+1]*v.y + bt[c+1], 0.f);
        v.z = fmaxf(gm[c+2]*v.z + bt[c+2], 0.f);
        v.w = fmaxf(gm[c+3]*v.w + bt[c+3], 0.f);
        #pragma unroll
        for (int k = 0; k < NCCL; k++) {
            acc[k] += v.x*ws[k*INNERC + c] + v.y*ws[k*INNERC + c + 1]
                    + v.z*ws[k*INNERC + c + 2] + v.w*ws[k*INNERC + c + 3];
        }
    }
    int best = 0; float bv = acc[0];
    #pragma unroll
    for (int k = 1; k < NCCL; k++) if (acc[k] > bv) { bv = acc[k]; best = k; }
    #pragma unroll
    for (int k = 0; k < NCCL; k++) res[((size_t)(b*NCCL + k))*HP + p] = acc[k];
    pred[gp] = best;
}

// per-class masked sums with fused BN affine+ReLU on raw fea
__global__ __launch_bounds__(256)
void region_partial_kernel(const float* __restrict__ fea, const int* __restrict__ pred,
                           const float* __restrict__ mean, const float* __restrict__ invstd,
                           const float* __restrict__ g, const float* __restrict__ bb,
                           float* __restrict__ psum, float* __restrict__ pcnt)
{
    __shared__ float acc[NCCL*INNERC];
    __shared__ float cnt[NCCL];
    int tid = threadIdx.x;
    for (int i = tid; i < NCCL*INNERC; i += 256) acc[i] = 0.f;
    if (tid < NCCL) cnt[tid] = 0.f;
    const float gmv = g[tid]*invstd[tid];
    const float btv = bb[tid] - mean[tid]*gmv;
    __syncthreads();
    int slice = blockIdx.x;
    int r0 = (int)((long long)ROWS * slice / RSLICE);
    int r1 = (int)((long long)ROWS * (slice + 1) / RSLICE);
    for (int r = r0; r < r1; ++r) {
        int k = pred[r];
        float v = fmaxf(gmv*fea[(size_t)r*INNERC + tid] + btv, 0.f);
        acc[k*INNERC + tid] += v;
        if (tid == 0) cnt[k] += 1.f;
    }
    __syncthreads();
    for (int i = tid; i < NCCL*INNERC; i += 256) psum[(size_t)slice*NCCL*INNERC + i] = acc[i];
    if (tid < NCCL) pcnt[slice*NCCL + tid] = cnt[tid];
}

__global__ void region_final_kernel(const float* __restrict__ psum, const float* __restrict__ pcnt,
                                    float* __restrict__ keys, float* __restrict__ counts)
{
    __shared__ float red[256];
    __shared__ float cs;
    int k = blockIdx.x, tid = threadIdx.x;
    float s = 0.f;
    for (int i = 0; i < RSLICE; i++) s += psum[(size_t)i*NCCL*INNERC + k*INNERC + tid];
    if (tid == 0) {
        float c = 0.f;
        for (int i = 0; i < RSLICE; i++) c += pcnt[i*NCCL + k];
        counts[k] = c; cs = c;
    }
    __syncthreads();
    float c = cs;
    float key = s / fmaxf(c, 1.f);
    red[tid] = key*key; __syncthreads();
    for (int o = 128; o > 0; o >>= 1) { if (tid < o) red[tid] += red[tid + o]; __syncthreads(); }
    float nrm = sqrtf(red[0]);
    keys[k*INNERC + tid] = key / fmaxf(nrm, 1e-12f);
}

__global__ __launch_bounds__(128)
void sims_kernel(const float* __restrict__ keys, const float* __restrict__ queues,
                 float* __restrict__ psume, float* __restrict__ adiag)
{
    __shared__ float ks[NCCL*INNERC];
    __shared__ float red[128];
    int tid = threadIdx.x;
    for (int i = tid; i < NCCL*INNERC; i += 128) ks[i] = keys[i];
    __syncthreads();
    int j = blockIdx.y, lc = blockIdx.x;
    int l = lc*LCHUNK + tid;
    float acc[NCCL];
    #pragma unroll
    for (int k = 0; k < NCCL; k++) acc[k] = 0.f;
    if (l < QLL) {
        const float* q = queues + (size_t)j*INNERC*QLL + l;
        #pragma unroll 4
        for (int c = 0; c < INNERC; ++c) {
            float qv = q[(size_t)c*QLL];
            #pragma unroll
            for (int k = 0; k < NCCL; k++) acc[k] += ks[k*INNERC + c]*qv;
        }
    }
    const float scale = 1.f/((float)INNERC*0.2f);
    for (int k = 0; k < NCCL; k++) {
        float a = acc[k]*scale;
        if (j == k && l < QLL) adiag[k*QLL + l] = a;
        red[tid] = (l < QLL) ? expf(a) : 0.f;
        __syncthreads();
        for (int o = 64; o > 0; o >>= 1) { if (tid < o) red[tid] += red[tid + o]; __syncthreads(); }
        if (tid == 0) psume[((size_t)k*NCCL + j)*NLCH + lc] = red[0];
        __syncthreads();
    }
}

// merged: lneg + per-class loss + final sum, one block of 256 threads
__global__ __launch_bounds__(256)
void loss_kernel(const float* __restrict__ psume, const float* __restrict__ adiag,
                 const float* __restrict__ counts, float* __restrict__ out, int idx)
{
    __shared__ float red[256];
    __shared__ float lneg[NCCL];
    int tid = threadIdx.x;
    if (tid < NCCL) {
        int k = tid;
        float tot = 0.f;
        for (int j = 0; j < NCCL; j++) {
            if (j == k) continue;
            for (int lc = 0; lc < NLCH; lc++) tot += psume[((size_t)k*NCCL + j)*NLCH + lc];
        }
        lneg[k] = logf(tot);
    }
    __syncthreads();
    float total = 0.f;   // accumulated on tid 0 across classes
    for (int k = 0; k < NCCL; k++) {
        float L = lneg[k];
        float s = 0.f;
        for (int l = tid; l < QLL; l += 256)
            s += log1pf(expf(L - adiag[k*QLL + l]));
        red[tid] = s; __syncthreads();
        for (int o = 128; o > 0; o >>= 1) { if (tid < o) red[tid] += red[tid + o]; __syncthreads(); }
        if (tid == 0 && counts[k] > 0.f) total += red[0]/(float)QLL;
        __syncthreads();
    }
    if (tid == 0) out[idx] = total;
}

// ------------------------- launch -------------------------
static float* sym_f(const void* s) { void* p = nullptr; cudaGetSymbolAddress(&p, s); return (float*)p; }
static __half* sym_h(const void* s) { void* p = nullptr; cudaGetSymbolAddress(&p, s); return (__half*)p; }

#define CONV_SMEM (4*16384)

extern "C" void kernel_launch(void* const* d_in, const int* in_sizes, int n_in,
                              void* d_out, int out_size)
{
    const float* x      = (const float*)d_in[0];
    const float* w_gp   = (const float*)d_in[1];
    const float* gg_gp  = (const float*)d_in[2];
    const float* gb_gp  = (const float*)d_in[3];
    const float* w_1x1  = (const float*)d_in[4];
    const float* ga_1   = (const float*)d_in[5];
    const float* gb_1   = (const float*)d_in[6];
    const float* w_d12  = (const float*)d_in[7];
    const float* ga_12  = (const float*)d_in[8];
    const float* gb_12  = (const float*)d_in[9];
    const float* w_d24  = (const float*)d_in[10];
    const float* ga_24  = (const float*)d_in[11];
    const float* gb_24  = (const float*)d_in[12];
    const float* w_d36  = (const float*)d_in[13];
    const float* ga_36  = (const float*)d_in[14];
    const float* gb_36  = (const float*)d_in[15];
    const float* w_head = (const float*)d_in[16];
    const float* ga_h   = (const float*)d_in[17];
    const float* gb_h   = (const float*)d_in[18];
    const float* w_fin  = (const float*)d_in[19];
    const float* b_fin  = (const float*)d_in[20];
    const float* queues = (const float*)d_in[21];
    float* out = (float*)d_out;

    __half* xh   = sym_h(sc_xh);
    __half* aspp_rawh = sym_h(sc_aspp_rawh);
    __half* aH   = sym_h(sc_asppH);
    float* fea   = sym_f(sc_fea);
    __half *w1h = sym_h(sc_w1h);
    __half *w12h = sym_h(sc_w12h);
    __half *w24h = sym_h(sc_w24h);
    __half *w36h = sym_h(sc_w36h);
    __half *whh = sym_h(sc_whh);
    float* gpp    = sym_f(sc_gpp);
    float* gpv    = sym_f(sc_gpv);
    float* z0     = sym_f(sc_z0);
    float* br0    = sym_f(sc_br0);
    float* psum   = sym_f(sc_psum);
    float* psq    = sym_f(sc_psq);
    float* meanv  = sym_f(sc_mean);
    float* invstd = sym_f(sc_invstd);
    float* mean2  = sym_f(sc_mean2);
    float* invstd2= sym_f(sc_invstd2);
    int*   pred;  { void* p = nullptr; cudaGetSymbolAddress(&p, sc_pred); pred = (int*)p; }
    float* rpsum  = sym_f(sc_rpsum);
    float* rpcnt  = sym_f(sc_rpcnt);
    float* keys   = sym_f(sc_keys);
    float* counts = sym_f(sc_counts);
    float* psume  = sym_f(sc_psume);
    float* adiag  = sym_f(sc_adiag);

    static int smem_set = 0;
    if (!smem_set) {
        cudaFuncSetAttribute(mma_conv_kernel<__half>, cudaFuncAttributeMaxDynamicSharedMemorySize, CONV_SMEM);
        cudaFuncSetAttribute(mma_conv_kernel<float>, cudaFuncAttributeMaxDynamicSharedMemorySize, CONV_SMEM);
        smem_set = 1;
    }

    // 1. input transpose + gp partials
    transpose_x_fp16_kernel<<<dim3(NPB, CINC/32, BATCH), dim3(32,8)>>>(x, xh, gpp);
    gp_final_kernel<<<(BATCH*CINC + 255)/256, 256>>>(gpp, gpv);

    // 2. all weight transforms in one launch (fp16, 32-ci stage blocks)
    {
        WtCfg wc;
        wc.src[0] = w_1x1;  wc.dh[0] = w1h;  wc.Cin[0] = CINC; wc.ntaps[0] = 1;
        wc.src[1] = w_d12;  wc.dh[1] = w12h; wc.Cin[1] = CINC; wc.ntaps[1] = 9;
        wc.src[2] = w_d24;  wc.dh[2] = w24h; wc.Cin[2] = CINC; wc.ntaps[2] = 9;
        wc.src[3] = w_d36;  wc.dh[3] = w36h; wc.Cin[3] = CINC; wc.ntaps[3] = 9;
        wc.src[4] = w_head; wc.dh[4] = whh;  wc.Cin[4] = NCAT; wc.ntaps[4] = 9;
        int acc = 0;
        for (int s = 0; s < 5; s++) { wc.base[s] = acc; acc += wc.ntaps[s]*wc.Cin[s]*INNERC; }
        wc.base[5] = acc;
        wtrans_all_kernel<<<(acc + 255)/256, 256>>>(wc);
    }

    // 3. global-pool branch
    z0_kernel<<<dim3(INNERC, BATCH), 256>>>(w_gp, gpv, z0);
    bn0_kernel<<<1, 256>>>(z0, gg_gp, gb_gp, br0);

    // 4. all four ASPP convs in ONE fused launch -> fp16 pre-BN buffer
    {
        ConvCfg cfg;
        cfg.wh[0] = w1h;  cfg.ntaps[0] = 1; cfg.dil[0] = 0;  cfg.off[0] = 0;
        cfg.wh[1] = w12h; cfg.ntaps[1] = 9; cfg.dil[1] = 12; cfg.off[1] = 256;
        cfg.wh[2] = w24h; cfg.ntaps[2] = 9; cfg.dil[2] = 24; cfg.off[2] = 512;
        cfg.wh[3] = w36h; cfg.ntaps[3] = 9; cfg.dil[3] = 36; cfg.off[3] = 768;
        dim3 grid(2, (HP + 127)/128, 4*BATCH);
        mma_conv_kernel<__half><<<grid, 256, CONV_SMEM>>>(xh, cfg, aspp_rawh, CINC, 1024);
    }

    // 5. BN + ReLU + concat -> fp16 plane
    stats_partial_kernel<__half><<<NSLICE, 256>>>(aspp_rawh, ROWS, 1024, 0, 1024, psum, psq);
    stats_final_kernel<<<4, 256>>>(psum, psq, 1024, ROWS, meanv, invstd);
    bn_apply_aspp_kernel<<<dim3((ROWS + 7)/8, 5), 256>>>(aspp_rawh, br0, meanv, invstd,
        ga_1, gb_1, ga_12, gb_12, ga_24, gb_24, ga_36, gb_36, aH);

    // 6. head conv (raw fp32 out) + BN stats (BN-apply fused into consumers)
    {
        ConvCfg cfg;
        cfg.wh[0] = whh; cfg.ntaps[0] = 9; cfg.dil[0] = 1; cfg.off[0] = 0;
        cfg.wh[1] = whh; cfg.ntaps[1] = 9; cfg.dil[1] = 1; cfg.off[1] = 0;
        cfg.wh[2] = whh; cfg.ntaps[2] = 9; cfg.dil[2] = 1; cfg.off[2] = 0;
        cfg.wh[3] = whh; cfg.ntaps[3] = 9; cfg.dil[3] = 1; cfg.off[3] = 0;
        dim3 grid(2, (HP + 127)/128, BATCH);
        mma_conv_kernel<float><<<grid, 256, CONV_SMEM>>>(aH, cfg, fea, NCAT, INNERC);
    }
    stats_partial_kernel<float><<<NSLICE, 256>>>(fea, ROWS, INNERC, 0, INNERC, psum, psq);
    stats_final_kernel<<<1, 256>>>(psum, psq, INNERC, ROWS, mean2, invstd2);

    // 7. classifier + argmax (BN affine fused; res straight to d_out)
    final_conv_kernel<<<(ROWS + 127)/128, 128>>>(fea, w_fin, b_fin,
                                                 mean2, invstd2, ga_h, gb_h, out, pred);

    // 8. region keys (BN affine fused)
    region_partial_kernel<<<RSLICE, 256>>>(fea, pred, mean2, invstd2, ga_h, gb_h, rpsum, rpcnt);
    region_final_kernel<<<NCCL, 256>>>(rpsum, rpcnt, keys, counts);

    // 9. contrast loss
    sims_kernel<<<dim3(NLCH, NCCL), 128>>>(keys, queues, psume, adiag);
    loss_kernel<<<1, 256>>>(psume, adiag, counts, out, out_size - 1);
}

// round 14
// speedup vs baseline: 1.5068x; 1.0453x over previous
#include <cuda_runtime.h>
#include <cuda_fp16.h>
#include <math.h>
#include <stdint.h>

#define BATCH 4
#define CINC 2048
#define HH 65
#define HP (HH*HH)          // 4225
#define INNERC 256
#define NCAT 1280
#define NCCL 19
#define QLL 2975
#define ROWS (BATCH*HP)     // 16900
#define NSLICE 512
#define RSLICE 64
#define LCHUNK 128
#define NLCH 24             // ceil(2975/128)
#define NPB 133             // ceil(HP/32) pixel blocks for gp partials

// ------------------------- static scratch (no allocation allowed) -------------------------
static __device__ __half sc_xh[(size_t)BATCH*HP*CINC];
static __device__ __half sc_aspp_rawh[(size_t)BATCH*HP*1024];    // pre-BN conv branches, fp16
static __device__ __half sc_asppH[(size_t)BATCH*HP*NCAT];
static __device__ float sc_fea[(size_t)BATCH*HP*INNERC];         // pre-BN head conv out
// blocked fp16 weights: [stage=(t,cc32)][256 co][32 ci]
static __device__ __half sc_w1h[CINC*INNERC];
static __device__ __half sc_w12h[9*CINC*INNERC];
static __device__ __half sc_w24h[9*CINC*INNERC];
static __device__ __half sc_w36h[9*CINC*INNERC];
static __device__ __half sc_whh[9*NCAT*INNERC];
static __device__ float sc_gpp[BATCH*NPB*CINC];              // gp partial sums
static __device__ float sc_gpv[BATCH*CINC];
static __device__ float sc_z0[BATCH*INNERC];
static __device__ float sc_br0[BATCH*INNERC];
static __device__ float sc_psum[NSLICE*1024];
static __device__ float sc_psq[NSLICE*1024];
static __device__ float sc_mean[1024];
static __device__ float sc_invstd[1024];
static __device__ float sc_mean2[INNERC];
static __device__ float sc_invstd2[INNERC];
static __device__ int   sc_pred[ROWS];
static __device__ float sc_rpsum[RSLICE*NCCL*INNERC];
static __device__ float sc_rpcnt[RSLICE*NCCL];
static __device__ float sc_keys[NCCL*INNERC];
static __device__ float sc_counts[NCCL];
static __device__ float sc_psume[NCCL*NCCL*NLCH];
static __device__ float sc_adiag[NCCL*QLL];
static __device__ float sc_lneg[NCCL];
static __device__ float sc_lossper[NCCL];

// ------------------------- helpers -------------------------
__device__ __forceinline__ uint32_t smem_u32(const void* p) {
    uint32_t a;
    asm("{ .reg .u64 t; cvta.to.shared.u64 t, %1; cvt.u32.u64 %0, t; }" : "=r"(a) : "l"(p));
    return a;
}
// 64B-row swizzle: XOR row bits (1,2) into 16B-granule bits
__device__ __forceinline__ uint32_t sw64(uint32_t off) { return off ^ ((off >> 3) & 0x30); }

__device__ __forceinline__ void cp16(uint32_t dst, const void* src, int sz) {
    asm volatile("cp.async.cg.shared.global [%0], [%1], 16, %2;"
                 :: "r"(dst), "l"(src), "r"(sz) : "memory");
}
#define CP_COMMIT() asm volatile("cp.async.commit_group;" ::: "memory")
#define CP_WAIT2()  asm volatile("cp.async.wait_group 2;" ::: "memory")

__device__ __forceinline__ void ldsm4(uint32_t* r, uint32_t addr) {
    asm volatile("ldmatrix.sync.aligned.m8n8.x4.shared.b16 {%0,%1,%2,%3}, [%4];"
                 : "=r"(r[0]), "=r"(r[1]), "=r"(r[2]), "=r"(r[3]) : "r"(addr));
}
__device__ __forceinline__ void mma16816(float* d, const uint32_t* a, uint32_t b0, uint32_t b1) {
    asm volatile("mma.sync.aligned.m16n8k16.row.col.f32.f16.f16.f32 "
                 "{%0,%1,%2,%3}, {%4,%5,%6,%7}, {%8,%9}, {%0,%1,%2,%3};"
                 : "+f"(d[0]), "+f"(d[1]), "+f"(d[2]), "+f"(d[3])
                 : "r"(a[0]), "r"(a[1]), "r"(a[2]), "r"(a[3]), "r"(b0), "r"(b1));
}
__device__ __forceinline__ void store2(float* p, float a, float b) { *(float2*)p = make_float2(a, b); }
__device__ __forceinline__ void store2(__half* p, float a, float b) { *(__half2*)p = __floats2half2_rn(a, b); }
__device__ __forceinline__ float ldf(const float* p) { return *p; }
__device__ __forceinline__ float ldf(const __half* p) { return __half2float(*p); }

struct ConvCfg {
    const __half* wh[4];
    int ntaps[4];
    int dil[4];
    int off[4];
};
struct WtCfg {
    const float* src[5];
    __half* dh[5];
    int Cin[5];
    int ntaps[5];
    int base[6];
};

// ------------------------- pre kernels -------------------------

// NCHW -> [b][p][ci] fp16 + global-pool partial sums
__global__ void transpose_x_fp16_kernel(const float* __restrict__ x,
                                        __half* __restrict__ xh, float* __restrict__ gpp)
{
    __shared__ float tile[32][33];
    __shared__ float red[32][8];
    int b = blockIdx.z;
    int p0 = blockIdx.x * 32, c0 = blockIdx.y * 32;
    int tx = threadIdx.x, ty = threadIdx.y; // 32 x 8
    #pragma unroll
    for (int i = 0; i < 32; i += 8) {
        int c = c0 + ty + i, p = p0 + tx;
        tile[ty + i][tx] = (p < HP) ? x[((size_t)b*CINC + c)*HP + p] : 0.f;
    }
    __syncthreads();
    #pragma unroll
    for (int i = 0; i < 32; i += 8) {
        int p = p0 + ty + i, c = c0 + tx;
        if (p < HP)
            xh[((size_t)b*HP + p)*CINC + c] = __float2half(tile[tx][ty + i]);
    }
    {
        float s = 0.f;
        #pragma unroll
        for (int j = 0; j < 4; j++) s += tile[tx][ty*4 + j];
        red[tx][ty] = s;
        __syncthreads();
        if (ty == 0) {
            float t = 0.f;
            #pragma unroll
            for (int k = 0; k < 8; k++) t += red[tx][k];
            gpp[((size_t)b*NPB + blockIdx.x)*CINC + c0 + tx] = t;
        }
    }
}

__global__ void gp_final_kernel(const float* __restrict__ gpp, float* __restrict__ gpv)
{
    int idx = blockIdx.x * 256 + threadIdx.x;   // (b,c)
    if (idx >= BATCH*CINC) return;
    int b = idx >> 11, c = idx & 2047;
    float s = 0.f;
    for (int k = 0; k < NPB; k++) s += gpp[((size_t)b*NPB + k)*CINC + c];
    gpv[idx] = s / (float)HP;
}

// all five weight transforms in one launch: w[co][ci][t] -> [stage=(t,cc32)][co 256][ci 32] fp16
__global__ void wtrans_all_kernel(WtCfg cfg)
{
    int idx = blockIdx.x * 256 + threadIdx.x;
    #pragma unroll
    for (int s = 0; s < 5; s++) {
        if (idx >= cfg.base[s] && idx < cfg.base[s+1]) {
            int li = idx - cfg.base[s];
            int Cin = cfg.Cin[s], ntaps = cfg.ntaps[s];
            int bi = li >> 13;           // 8192 elems per stage block
            int r = li & 8191;
            int co = r >> 5, cil = r & 31;
            int nch = Cin >> 5;
            int t = bi / nch, cc = bi - t*nch;
            int ci = cc*32 + cil;
            float v = cfg.src[s][((size_t)co*Cin + ci)*ntaps + t];
            cfg.dh[s][li] = __float2half(v);
            return;
        }
    }
}

__global__ void z0_kernel(const float* __restrict__ w_gp, const float* __restrict__ gpv, float* __restrict__ z0)
{
    __shared__ float red[256];
    int co = blockIdx.x, b = blockIdx.y;
    float s = 0.f;
    for (int ci = threadIdx.x; ci < CINC; ci += 256)
        s += w_gp[(size_t)co*CINC + ci] * gpv[b*CINC + ci];
    red[threadIdx.x] = s; __syncthreads();
    for (int o = 128; o > 0; o >>= 1) { if (threadIdx.x < o) red[threadIdx.x] += red[threadIdx.x + o]; __syncthreads(); }
    if (threadIdx.x == 0) z0[b*INNERC + co] = red[0];
}

__global__ void bn0_kernel(const float* __restrict__ z0, const float* __restrict__ g,
                           const float* __restrict__ bb, float* __restrict__ br0)
{
    int c = threadIdx.x;
    float m = 0.f;
    for (int b = 0; b < 4; b++) m += z0[b*INNERC + c];
    m *= 0.25f;
    float v = 0.f;
    for (int b = 0; b < 4; b++) { float d = z0[b*INNERC + c] - m; v += d*d; }
    v *= 0.25f;
    float is = rsqrtf(v + 1e-5f);
    for (int b = 0; b < 4; b++) {
        float val = g[c]*(z0[b*INNERC + c] - m)*is + bb[c];
        br0[b*INNERC + c] = fmaxf(val, 0.f);
    }
}

// ------------------------- mma.sync conv kernel -------------------------
// CTA: 128 pixels x 128 co, 8 warps (4x2), warp 32x64, pure fp16, fp32 accum
// K-chunk 32, stage = 16KB (A 8K | B 8K), 4-deep ring, wait_group 2, 2 CTAs/SM.
// Fully-OOB tap stages skipped (compacted valid-stage sequence).
#define STAGE_BYTES 16384u

template<typename OutT>
__global__ __launch_bounds__(256, 2)
void mma_conv_kernel(const __half* __restrict__ Ahp,
                     ConvCfg cfg, OutT* __restrict__ outbuf, int Cin, int outStride)
{
    extern __shared__ char smem[];
    const uint32_t sbase = smem_u32(smem);
    const int tid = threadIdx.x;
    const int wid = tid >> 5, lane = tid & 31;
    const int branch = blockIdx.z >> 2;
    const int b = blockIdx.z & 3;
    const __half* Bhp = cfg.wh[branch];
    const int ntaps = cfg.ntaps[branch];
    const int dil = cfg.dil[branch];
    const int outOff = cfg.off[branch];
    const int p0 = blockIdx.y * 128;
    const int co0 = blockIdx.x * 128;
    const int nchunk = Cin >> 5;
    const int nstage = ntaps * nchunk;

    const int h_lo = p0 / HH;
    const int h_hi = (p0 + 127 < HP ? p0 + 127 : HP - 1) / HH;

    auto skipstage = [&](int i) -> bool {
        if (ntaps != 9) return false;
        int t = i / nchunk;
        int dh = (t/3 - 1) * dil;
        return (h_hi + dh < 0) || (h_lo + dh > HH - 1);
    };
    auto nextv = [&](int i) -> int {
        while (i < nstage && skipstage(i)) ++i;
        return i;
    };

    // loader role: tid 0-127 load A rows, tid 128-255 load B rows (64B each)
    const int isB = tid >> 7;
    const int lrow = tid & 127;

    const int pA = p0 + lrow;
    const int hA = pA / HH, wA = pA - hA*HH;

    uint32_t soff[4];
    #pragma unroll
    for (int j = 0; j < 4; j++)
        soff[j] = sw64((uint32_t)lrow*64u + j*16u) + (uint32_t)isB*8192u;

    auto issue = [&](int i, int buf) {
        int t = i / nchunk;
        int cc = i - t*nchunk;
        uint32_t sb = sbase + (uint32_t)buf * STAGE_BYTES;
        if (!isB) {
            int c0 = cc << 5;
            int dh = (ntaps == 9) ? (t/3 - 1)*dil : 0;
            int dw = (ntaps == 9) ? (t - (t/3)*3 - 1)*dil : 0;
            int hh = hA + dh, ww = wA + dw;
            bool ok = (pA < HP) && (hh >= 0) && (hh < HH) && (ww >= 0) && (ww < HH);
            const char* asrc = (const char*)(Ahp + ((size_t)(b*HP + (ok ? (hh*HH + ww) : 0)))*Cin + c0);
            int sz = ok ? 16 : 0;
            #pragma unroll
            for (int j = 0; j < 4; j++)
                cp16(sb + soff[j], asrc + j*16, sz);
        } else {
            const char* bsrc = (const char*)(Bhp + (size_t)i*8192 + (size_t)(co0 + lrow)*32);
            #pragma unroll
            for (int j = 0; j < 4; j++)
                cp16(sb + soff[j], bsrc + j*16, 16);
        }
    };

    const int wm = wid >> 1;
    const int wn = wid & 1;
    const int ar = lane & 15;
    const int acolsel = (lane >> 4) << 4;
    const int br = (lane & 7) + ((lane >> 4) << 3);
    const int bcolsel = (lane & 8) ? 16 : 0;

    float acc[2][8][4];
    #pragma unroll
    for (int m = 0; m < 2; m++)
        #pragma unroll
        for (int j = 0; j < 8; j++)
            #pragma unroll
            for (int e = 0; e < 4; e++) acc[m][j][e] = 0.f;

    // compacted valid-stage pipeline with 3 stages of look-ahead (4-deep ring)
    int s0 = nextv(0);
    int s1 = (s0 < nstage) ? nextv(s0 + 1) : nstage;
    int s2 = (s1 < nstage) ? nextv(s1 + 1) : nstage;
    int s3 = (s2 < nstage) ? nextv(s2 + 1) : nstage;

    issue(s0, 0); CP_COMMIT();
    if (s1 < nstage) issue(s1, 1);
    CP_COMMIT();
    if (s2 < nstage) issue(s2, 2);
    CP_COMMIT();

    int bi = 0;
    while (s0 < nstage) {
        CP_WAIT2();            // pending {bi,bi+1,bi+2} -> group bi complete
        __syncthreads();       // visibility + protects ring reuse
        if (s3 < nstage) issue(s3, (bi + 3) & 3);
        CP_COMMIT();

        uint32_t sb = sbase + (uint32_t)(bi & 3) * STAGE_BYTES;
        #pragma unroll
        for (int ks = 0; ks < 2; ks++) {
            uint32_t a_h[2][4];
            #pragma unroll
            for (int m = 0; m < 2; m++) {
                uint32_t off = sw64((uint32_t)(wm*32 + m*16 + ar)*64u + (uint32_t)(ks*32 + acolsel));
                ldsm4(a_h[m], sb + off);
            }
            #pragma unroll
            for (int nb = 0; nb < 4; nb++) {
                uint32_t offb = sw64((uint32_t)(wn*64 + nb*16 + br)*64u + (uint32_t)(ks*32 + bcolsel));
                uint32_t b_h[4];
                ldsm4(b_h, sb + 8192u + offb);
                #pragma unroll
                for (int m = 0; m < 2; m++)
                    #pragma unroll
                    for (int h2 = 0; h2 < 2; h2++) {
                        mma16816(acc[m][nb*2 + h2], a_h[m], b_h[h2*2], b_h[h2*2 + 1]);
                    }
            }
        }

        s0 = s1; s1 = s2; s2 = s3;
        s3 = (s3 < nstage) ? nextv(s3 + 1) : nstage;
        bi++;
    }

    #pragma unroll
    for (int m = 0; m < 2; m++) {
        #pragma unroll
        for (int e2 = 0; e2 < 2; e2++) {
            int p = p0 + wm*32 + m*16 + (lane >> 2) + e2*8;
            if (p >= HP) continue;
            OutT* orow = outbuf + ((size_t)b*HP + p)*outStride + outOff + co0 + wn*64 + 2*(lane & 3);
            #pragma unroll
            for (int j = 0; j < 8; j++)
                store2(orow + j*8, acc[m][j][e2*2], acc[m][j][e2*2 + 1]);
        }
    }
}

// ------------------------- BN / epilogue kernels -------------------------
template<typename T>
__global__ void stats_partial_kernel(const T* __restrict__ buf, int rows, int cstride, int coff,
                                     int nch, float* __restrict__ psum, float* __restrict__ psq)
{
    int slice = blockIdx.x;
    int r0 = (int)((long long)rows * slice / NSLICE);
    int r1 = (int)((long long)rows * (slice + 1) / NSLICE);
    for (int c = threadIdx.x; c < nch; c += 256) {
        float s = 0.f, q = 0.f;
        for (int r = r0; r < r1; ++r) {
            float v = ldf(&buf[(size_t)r*cstride + coff + c]);
            s += v; q += v*v;
        }
        psum[(size_t)slice*nch + c] = s;
        psq [(size_t)slice*nch + c] = q;
    }
}

__global__ void stats_final_kernel(const float* __restrict__ psum, const float* __restrict__ psq,
                                   int nch, int rows, float* __restrict__ mean, float* __restrict__ invstd)
{
    int c = blockIdx.x * 256 + threadIdx.x;
    if (c >= nch) return;
    float s = 0.f, q = 0.f;
    for (int i = 0; i < NSLICE; i++) { s += psum[(size_t)i*nch + c]; q += psq[(size_t)i*nch + c]; }
    float m = s / (float)rows;
    float v = q / (float)rows - m*m;
    mean[c] = m;
    invstd[c] = rsqrtf(v + 1e-5f);
}

// aspp_rawh (fp16, 1024ch) + br0 -> fp16 concat plane (1280ch) with BN+ReLU
__global__ __launch_bounds__(256)
void bn_apply_aspp_kernel(const __half* __restrict__ raw, const float* __restrict__ br0,
    const float* __restrict__ mean, const float* __restrict__ invstd,
    const float* __restrict__ g1, const float* __restrict__ b1,
    const float* __restrict__ g2, const float* __restrict__ b2,
    const float* __restrict__ g3, const float* __restrict__ b3,
    const float* __restrict__ g4, const float* __restrict__ b4,
    __half* __restrict__ oh)
{
    const int cb = blockIdx.y;            // 0..4 channel block of 256
    const int c = threadIdx.x;
    const int bp0 = blockIdx.x * 8;
    if (cb == 0) {
        #pragma unroll
        for (int i = 0; i < 8; i++) {
            int bp = bp0 + i;
            if (bp >= ROWS) break;
            int b = bp / HP;
            oh[(size_t)bp*NCAT + c] = __float2half(br0[b*INNERC + c]);
        }
        return;
    }
    const int ch = (cb - 1)*256 + c;
    const float* g; const float* bb;
    if (cb == 1)      { g = g1; bb = b1; }
    else if (cb == 2) { g = g2; bb = b2; }
    else if (cb == 3) { g = g3; bb = b3; }
    else              { g = g4; bb = b4; }
    const float gm = g[c]*invstd[ch];
    const float bt = bb[c] - mean[ch]*gm;
    #pragma unroll
    for (int i = 0; i < 8; i++) {
        int bp = bp0 + i;
        if (bp >= ROWS) break;
        float v = fmaxf(gm*__half2float(raw[(size_t)bp*1024 + ch]) + bt, 0.f);
        oh[(size_t)bp*NCAT + cb*256 + c] = __float2half(v);
    }
}

// classifier + argmax with fused BN affine+ReLU on raw fea
__global__ __launch_bounds__(128)
void final_conv_kernel(const float* __restrict__ fea, const float* __restrict__ w_fin,
                       const float* __restrict__ b_fin,
                       const float* __restrict__ mean, const float* __restrict__ invstd,
                       const float* __restrict__ g, const float* __restrict__ bb,
                       float* __restrict__ res, int* __restrict__ pred)
{
    __shared__ float ws[NCCL*INNERC];
    __shared__ float bs[NCCL];
    __shared__ float gm[INNERC];
    __shared__ float bt[INNERC];
    for (int i = threadIdx.x; i < NCCL*INNERC; i += 128) ws[i] = w_fin[i];
    if (threadIdx.x < NCCL) bs[threadIdx.x] = b_fin[threadIdx.x];
    for (int i = threadIdx.x; i < INNERC; i += 128) {
        float gmv = g[i]*invstd[i];
        gm[i] = gmv;
        bt[i] = bb[i] - mean[i]*gmv;
    }
    __syncthreads();
    int gp = blockIdx.x * 128 + threadIdx.x;
    if (gp >= ROWS) return;
    int b = gp / HP, p = gp % HP;
    const float* f = fea + (size_t)gp * INNERC;
    float acc[NCCL];
    #pragma unroll
    for (int k = 0; k < NCCL; k++) acc[k] = bs[k];
    for (int c = 0; c < INNERC; c += 4) {
        float4 v = *(const float4*)(f + c);
        v.x = fmaxf(gm[c  ]*v.x + bt[c  ], 0.f);
        v.y = fmaxf(gm[c+1]*v.y + bt[c+1], 0.f);
        v.z = fmaxf(gm[c+2]*v.z + bt[c+2], 0.f);
        v.w = fmaxf(gm[c+3]*v.w + bt[c+3], 0.f);
        #pragma unroll
        for (int k = 0; k < NCCL; k++) {
            acc[k] += v.x*ws[k*INNERC + c] + v.y*ws[k*INNERC + c + 1]
                    + v.z*ws[k*INNERC + c + 2] + v.w*ws[k*INNERC + c + 3];
        }
    }
    int best = 0; float bv = acc[0];
    #pragma unroll
    for (int k = 1; k < NCCL; k++) if (acc[k] > bv) { bv = acc[k]; best = k; }
    #pragma unroll
    for (int k = 0; k < NCCL; k++) res[((size_t)(b*NCCL + k))*HP + p] = acc[k];
    pred[gp] = best;
}

// per-class masked sums with fused BN affine+ReLU on raw fea
__global__ __launch_bounds__(256)
void region_partial_kernel(const float* __restrict__ fea, const int* __restrict__ pred,
                           const float* __restrict__ mean, const float* __restrict__ invstd,
                           const float* __restrict__ g, const float* __restrict__ bb,
                           float* __restrict__ psum, float* __restrict__ pcnt)
{
    __shared__ float acc[NCCL*INNERC];
    __shared__ float cnt[NCCL];
    int tid = threadIdx.x;
    for (int i = tid; i < NCCL*INNERC; i += 256) acc[i] = 0.f;
    if (tid < NCCL) cnt[tid] = 0.f;
    const float gmv = g[tid]*invstd[tid];
    const float btv = bb[tid] - mean[tid]*gmv;
    __syncthreads();
    int slice = blockIdx.x;
    int r0 = (int)((long long)ROWS * slice / RSLICE);
    int r1 = (int)((long long)ROWS * (slice + 1) / RSLICE);
    for (int r = r0; r < r1; ++r) {
        int k = pred[r];
        float v = fmaxf(gmv*fea[(size_t)r*INNERC + tid] + btv, 0.f);
        acc[k*INNERC + tid] += v;
        if (tid == 0) cnt[k] += 1.f;
    }
    __syncthreads();
    for (int i = tid; i < NCCL*INNERC; i += 256) psum[(size_t)slice*NCCL*INNERC + i] = acc[i];
    if (tid < NCCL) pcnt[slice*NCCL + tid] = cnt[tid];
}

__global__ void region_final_kernel(const float* __restrict__ psum, const float* __restrict__ pcnt,
                                    float* __restrict__ keys, float* __restrict__ counts)
{
    __shared__ float red[256];
    __shared__ float cs;
    int k = blockIdx.x, tid = threadIdx.x;
    float s = 0.f;
    for (int i = 0; i < RSLICE; i++) s += psum[(size_t)i*NCCL*INNERC + k*INNERC + tid];
    if (tid == 0) {
        float c = 0.f;
        for (int i = 0; i < RSLICE; i++) c += pcnt[i*NCCL + k];
        counts[k] = c; cs = c;
    }
    __syncthreads();
    float c = cs;
    float key = s / fmaxf(c, 1.f);
    red[tid] = key*key; __syncthreads();
    for (int o = 128; o > 0; o >>= 1) { if (tid < o) red[tid] += red[tid + o]; __syncthreads(); }
    float nrm = sqrtf(red[0]);
    keys[k*INNERC + tid] = key / fmaxf(nrm, 1e-12f);
}

__global__ __launch_bounds__(128)
void sims_kernel(const float* __restrict__ keys, const float* __restrict__ queues,
                 float* __restrict__ psume, float* __restrict__ adiag)
{
    __shared__ float ks[NCCL*INNERC];
    __shared__ float red[128];
    int tid = threadIdx.x;
    for (int i = tid; i < NCCL*INNERC; i += 128) ks[i] = keys[i];
    __syncthreads();
    int j = blockIdx.y, lc = blockIdx.x;
    int l = lc*LCHUNK + tid;
    float acc[NCCL];
    #pragma unroll
    for (int k = 0; k < NCCL; k++) acc[k] = 0.f;
    if (l < QLL) {
        const float* q = queues + (size_t)j*INNERC*QLL + l;
        #pragma unroll 4
        for (int c = 0; c < INNERC; ++c) {
            float qv = q[(size_t)c*QLL];
            #pragma unroll
            for (int k = 0; k < NCCL; k++) acc[k] += ks[k*INNERC + c]*qv;
        }
    }
    const float scale = 1.f/((float)INNERC*0.2f);
    for (int k = 0; k < NCCL; k++) {
        float a = acc[k]*scale;
        if (j == k && l < QLL) adiag[k*QLL + l] = a;
        red[tid] = (l < QLL) ? expf(a) : 0.f;
        __syncthreads();
        for (int o = 64; o > 0; o >>= 1) { if (tid < o) red[tid] += red[tid + o]; __syncthreads(); }
        if (tid == 0) psume[((size_t)k*NCCL + j)*NLCH + lc] = red[0];
        __syncthreads();
    }
}

__global__ void lneg_kernel(const float* __restrict__ psume, float* __restrict__ lneg)
{
    int k = threadIdx.x;
    if (k >= NCCL) return;
    float tot = 0.f;
    for (int j = 0; j < NCCL; j++) {
        if (j == k) continue;
        for (int lc = 0; lc < NLCH; lc++) tot += psume[((size_t)k*NCCL + j)*NLCH + lc];
    }
    lneg[k] = logf(tot);
}

__global__ void lossper_kernel(const float* __restrict__ adiag, const float* __restrict__ lneg,
                               const float* __restrict__ counts, float* __restrict__ lossper)
{
    __shared__ float red[256];
    int k = blockIdx.x, tid = threadIdx.x;
    float L = lneg[k];
    float s = 0.f;
    for (int l = tid; l < QLL; l += 256)
        s += log1pf(expf(L - adiag[k*QLL + l]));
    red[tid] = s; __syncthreads();
    for (int o = 128; o > 0; o >>= 1) { if (tid < o) red[tid] += red[tid + o]; __syncthreads(); }
    if (tid == 0) lossper[k] = (counts[k] > 0.f) ? red[0]/(float)QLL : 0.f;
}

__global__ void loss_final_kernel(const float* __restrict__ lossper, float* __restrict__ out, int idx)
{
    if (threadIdx.x == 0 && blockIdx.x == 0) {
        float s = 0.f;
        for (int k = 0; k < NCCL; k++) s += lossper[k];
        out[idx] = s;
    }
}

// ------------------------- launch -------------------------
static float* sym_f(const void* s) { void* p = nullptr; cudaGetSymbolAddress(&p, s); return (float*)p; }
static __half* sym_h(const void* s) { void* p = nullptr; cudaGetSymbolAddress(&p, s); return (__half*)p; }

#define CONV_SMEM (4*16384)

extern "C" void kernel_launch(void* const* d_in, const int* in_sizes, int n_in,
                              void* d_out, int out_size)
{
    const float* x      = (const float*)d_in[0];
    const float* w_gp   = (const float*)d_in[1];
    const float* gg_gp  = (const float*)d_in[2];
    const float* gb_gp  = (const float*)d_in[3];
    const float* w_1x1  = (const float*)d_in[4];
    const float* ga_1   = (const float*)d_in[5];
    const float* gb_1   = (const float*)d_in[6];
    const float* w_d12  = (const float*)d_in[7];
    const float* ga_12  = (const float*)d_in[8];
    const float* gb_12  = (const float*)d_in[9];
    const float* w_d24  = (const float*)d_in[10];
    const float* ga_24  = (const float*)d_in[11];
    const float* gb_24  = (const float*)d_in[12];
    const float* w_d36  = (const float*)d_in[13];
    const float* ga_36  = (const float*)d_in[14];
    const float* gb_36  = (const float*)d_in[15];
    const float* w_head = (const float*)d_in[16];
    const float* ga_h   = (const float*)d_in[17];
    const float* gb_h   = (const float*)d_in[18];
    const float* w_fin  = (const float*)d_in[19];
    const float* b_fin  = (const float*)d_in[20];
    const float* queues = (const float*)d_in[21];
    float* out = (float*)d_out;

    __half* xh   = sym_h(sc_xh);
    __half* aspp_rawh = sym_h(sc_aspp_rawh);
    __half* aH   = sym_h(sc_asppH);
    float* fea   = sym_f(sc_fea);
    __half *w1h = sym_h(sc_w1h);
    __half *w12h = sym_h(sc_w12h);
    __half *w24h = sym_h(sc_w24h);
    __half *w36h = sym_h(sc_w36h);
    __half *whh = sym_h(sc_whh);
    float* gpp    = sym_f(sc_gpp);
    float* gpv    = sym_f(sc_gpv);
    float* z0     = sym_f(sc_z0);
    float* br0    = sym_f(sc_br0);
    float* psum   = sym_f(sc_psum);
    float* psq    = sym_f(sc_psq);
    float* meanv  = sym_f(sc_mean);
    float* invstd = sym_f(sc_invstd);
    float* mean2  = sym_f(sc_mean2);
    float* invstd2= sym_f(sc_invstd2);
    int*   pred;  { void* p = nullptr; cudaGetSymbolAddress(&p, sc_pred); pred = (int*)p; }
    float* rpsum  = sym_f(sc_rpsum);
    float* rpcnt  = sym_f(sc_rpcnt);
    float* keys   = sym_f(sc_keys);
    float* counts = sym_f(sc_counts);
    float* psume  = sym_f(sc_psume);
    float* adiag  = sym_f(sc_adiag);
    float* lneg   = sym_f(sc_lneg);
    float* lossper= sym_f(sc_lossper);

    static int smem_set = 0;
    if (!smem_set) {
        cudaFuncSetAttribute(mma_conv_kernel<__half>, cudaFuncAttributeMaxDynamicSharedMemorySize, CONV_SMEM);
        cudaFuncSetAttribute(mma_conv_kernel<float>, cudaFuncAttributeMaxDynamicSharedMemorySize, CONV_SMEM);
        smem_set = 1;
    }

    // 1. input transpose + gp partials
    transpose_x_fp16_kernel<<<dim3(NPB, CINC/32, BATCH), dim3(32,8)>>>(x, xh, gpp);
    gp_final_kernel<<<(BATCH*CINC + 255)/256, 256>>>(gpp, gpv);

    // 2. all weight transforms in one launch (fp16, 32-ci stage blocks)
    {
        WtCfg wc;
        wc.src[0] = w_1x1;  wc.dh[0] = w1h;  wc.Cin[0] = CINC; wc.ntaps[0] = 1;
        wc.src[1] = w_d12;  wc.dh[1] = w12h; wc.Cin[1] = CINC; wc.ntaps[1] = 9;
        wc.src[2] = w_d24;  wc.dh[2] = w24h; wc.Cin[2] = CINC; wc.ntaps[2] = 9;
        wc.src[3] = w_d36;  wc.dh[3] = w36h; wc.Cin[3] = CINC; wc.ntaps[3] = 9;
        wc.src[4] = w_head; wc.dh[4] = whh;  wc.Cin[4] = NCAT; wc.ntaps[4] = 9;
        int acc = 0;
        for (int s = 0; s < 5; s++) { wc.base[s] = acc; acc += wc.ntaps[s]*wc.Cin[s]*INNERC; }
        wc.base[5] = acc;
        wtrans_all_kernel<<<(acc + 255)/256, 256>>>(wc);
    }

    // 3. global-pool branch
    z0_kernel<<<dim3(INNERC, BATCH), 256>>>(w_gp, gpv, z0);
    bn0_kernel<<<1, 256>>>(z0, gg_gp, gb_gp, br0);

    // 4. all four ASPP convs in ONE fused launch, LONGEST-WORK-FIRST branch order
    //    (d12 has the most valid stages, then d24, d36; 1x1 shortest -> tail wave)
    {
        ConvCfg cfg;
        cfg.wh[0] = w12h; cfg.ntaps[0] = 9; cfg.dil[0] = 12; cfg.off[0] = 256;
        cfg.wh[1] = w24h; cfg.ntaps[1] = 9; cfg.dil[1] = 24; cfg.off[1] = 512;
        cfg.wh[2] = w36h; cfg.ntaps[2] = 9; cfg.dil[2] = 36; cfg.off[2] = 768;
        cfg.wh[3] = w1h;  cfg.ntaps[3] = 1; cfg.dil[3] = 0;  cfg.off[3] = 0;
        dim3 grid(2, (HP + 127)/128, 4*BATCH);
        mma_conv_kernel<__half><<<grid, 256, CONV_SMEM>>>(xh, cfg, aspp_rawh, CINC, 1024);
    }

    // 5. BN + ReLU + concat -> fp16 plane
    stats_partial_kernel<__half><<<NSLICE, 256>>>(aspp_rawh, ROWS, 1024, 0, 1024, psum, psq);
    stats_final_kernel<<<4, 256>>>(psum, psq, 1024, ROWS, meanv, invstd);
    bn_apply_aspp_kernel<<<dim3((ROWS + 7)/8, 5), 256>>>(aspp_rawh, br0, meanv, invstd,
        ga_1, gb_1, ga_12, gb_12, ga_24, gb_24, ga_36, gb_36, aH);

    // 6. head conv (raw fp32 out) + BN stats (BN-apply fused into consumers)
    {
        ConvCfg cfg;
        cfg.wh[0] = whh; cfg.ntaps[0] = 9; cfg.dil[0] = 1; cfg.off[0] = 0;
        cfg.wh[1] = whh; cfg.ntaps[1] = 9; cfg.dil[1] = 1; cfg.off[1] = 0;
        cfg.wh[2] = whh; cfg.ntaps[2] = 9; cfg.dil[2] = 1; cfg.off[2] = 0;
        cfg.wh[3] = whh; cfg.ntaps[3] = 9; cfg.dil[3] = 1; cfg.off[3] = 0;
        dim3 grid(2, (HP + 127)/128, BATCH);
        mma_conv_kernel<float><<<grid, 256, CONV_SMEM>>>(aH, cfg, fea, NCAT, INNERC);
    }
    stats_partial_kernel<float><<<NSLICE, 256>>>(fea, ROWS, INNERC, 0, INNERC, psum, psq);
    stats_final_kernel<<<1, 256>>>(psum, psq, INNERC, ROWS, mean2, invstd2);

    // 7. classifier + argmax (BN affine fused; res straight to d_out)
    final_conv_kernel<<<(ROWS + 127)/128, 128>>>(fea, w_fin, b_fin,
                                                 mean2, invstd2, ga_h, gb_h, out, pred);

    // 8. region keys (BN affine fused)
    region_partial_kernel<<<RSLICE, 256>>>(fea, pred, mean2, invstd2, ga_h, gb_h, rpsum, rpcnt);
    region_final_kernel<<<NCCL, 256>>>(rpsum, rpcnt, keys, counts);

    // 9. contrast loss (parallel 3-kernel path, as in best-measured R10)
    sims_kernel<<<dim3(NLCH, NCCL), 128>>>(keys, queues, psume, adiag);
    lneg_kernel<<<1, 32>>>(psume, lneg);
    lossper_kernel<<<NCCL, 256>>>(adiag, lneg, counts, lossper);
    loss_final_kernel<<<1, 1>>>(lossper, out, out_size - 1);
}